// round 12
// baseline (speedup 1.0000x reference)
#include <cuda_runtime.h>
#include <cuda_bf16.h>
#include <math.h>
#include <stdint.h>

// Problem constants
#define BB   2
#define SS   2048
#define HIDD 4096
#define NHH  32
#define NKVV 8
#define HDD  128
#define GG   4

#define N_HS ((size_t)BB * SS * HIDD)
#define N_WQ ((size_t)HIDD * HIDD)
#define N_WK ((size_t)NKVV * HDD * HIDD)
#define N_QB ((size_t)BB * NHH * SS * HDD)
#define N_KB ((size_t)BB * NKVV * SS * HDD)

// fp32 intermediates (pre-RoPE)
__device__ float g_Q[N_QB];
__device__ float g_K[N_KB];

// RoPE inverse-frequency table (double, precomputed once)
__device__ double g_invf[64];

// bf16 hi/lo split operands
__device__ __nv_bfloat16 g_hsh[N_HS],  g_hsl[N_HS];
__device__ __nv_bfloat16 g_Wqh[N_WQ],  g_Wql[N_WQ];
__device__ __nv_bfloat16 g_Wkh[N_WK],  g_Wkl[N_WK];
__device__ __nv_bfloat16 g_Wvh[N_WK],  g_Wvl[N_WK];
__device__ __nv_bfloat16 g_Woh[N_WQ],  g_Wol[N_WQ];
__device__ __nv_bfloat16 g_Qbh[N_QB],  g_Qbl[N_QB];   // post-RoPE, pre-scaled
__device__ __nv_bfloat16 g_Kbh[N_KB],  g_Kbl[N_KB];   // post-RoPE
__device__ __nv_bfloat16 g_Vbh[N_KB],  g_Vbl[N_KB];   // written by fused QKV GEMM
__device__ __nv_bfloat16 g_AOh[N_HS],  g_AOl[N_HS];   // attention output

// ---------------------------------------------------------------------------
// helpers
// ---------------------------------------------------------------------------
__device__ __forceinline__ uint32_t sptr(const void* p) {
    return (uint32_t)__cvta_generic_to_shared(p);
}
__device__ __forceinline__ void cp16(uint32_t d, const void* s) {
    asm volatile("cp.async.cg.shared.global [%0], [%1], 16;\n" :: "r"(d), "l"(s));
}
__device__ __forceinline__ void cp_commit() { asm volatile("cp.async.commit_group;\n"); }
template <int N> __device__ __forceinline__ void cp_wait() {
    asm volatile("cp.async.wait_group %0;\n" :: "n"(N));
}
__device__ __forceinline__ void ldm4(uint32_t* r, uint32_t a) {
    asm volatile("ldmatrix.sync.aligned.m8n8.x4.shared.b16 {%0,%1,%2,%3}, [%4];\n"
        : "=r"(r[0]), "=r"(r[1]), "=r"(r[2]), "=r"(r[3]) : "r"(a));
}
__device__ __forceinline__ void ldm4t(uint32_t* r, uint32_t a) {
    asm volatile("ldmatrix.sync.aligned.m8n8.x4.trans.shared.b16 {%0,%1,%2,%3}, [%4];\n"
        : "=r"(r[0]), "=r"(r[1]), "=r"(r[2]), "=r"(r[3]) : "r"(a));
}
__device__ __forceinline__ void mma_bf16(float* c, const uint32_t* a, uint32_t b0, uint32_t b1) {
    asm volatile(
        "mma.sync.aligned.m16n8k16.row.col.f32.bf16.bf16.f32 "
        "{%0,%1,%2,%3}, {%4,%5,%6,%7}, {%8,%9}, {%0,%1,%2,%3};\n"
        : "+f"(c[0]), "+f"(c[1]), "+f"(c[2]), "+f"(c[3])
        : "r"(a[0]), "r"(a[1]), "r"(a[2]), "r"(a[3]), "r"(b0), "r"(b1));
}
__device__ __forceinline__ void split2(float x, __nv_bfloat16& h, __nv_bfloat16& l) {
    h = __float2bfloat16(x);
    l = __float2bfloat16(x - __bfloat162float(h));
}

// ---------------------------------------------------------------------------
// Precompute inv-freq table (same expression -> bit-identical phases)
// ---------------------------------------------------------------------------
__global__ void invf_kernel()
{
    const int d = threadIdx.x;  // 0..63
    g_invf[d] = pow(10000.0, -(double)d / 64.0);
}

// ---------------------------------------------------------------------------
// Elementwise fp32 -> bf16 hi/lo split (inputs only).
// ---------------------------------------------------------------------------
__global__ void __launch_bounds__(256) split_kernel(const float* __restrict__ src,
                                                    int dsel, size_t n)
{
    __nv_bfloat16 *dh, *dl;
    switch (dsel) {
        case 1: dh = g_Wqh; dl = g_Wql; break;
        case 2: dh = g_Wkh; dl = g_Wkl; break;
        case 3: dh = g_Wvh; dl = g_Wvl; break;
        case 4: dh = g_Woh; dl = g_Wol; break;
        default: dh = g_hsh; dl = g_hsl; break;
    }
    const size_t i = ((size_t)blockIdx.x * 256 + threadIdx.x) * 4;
    if (i >= n) return;
    float4 v = *(const float4*)(src + i);
    __nv_bfloat16 h0, l0, h1, l1, h2, l2, h3, l3;
    split2(v.x, h0, l0); split2(v.y, h1, l1);
    split2(v.z, h2, l2); split2(v.w, h3, l3);
    ushort4 uh, ul;
    uh.x = __bfloat16_as_ushort(h0); uh.y = __bfloat16_as_ushort(h1);
    uh.z = __bfloat16_as_ushort(h2); uh.w = __bfloat16_as_ushort(h3);
    ul.x = __bfloat16_as_ushort(l0); ul.y = __bfloat16_as_ushort(l1);
    ul.z = __bfloat16_as_ushort(l2); ul.w = __bfloat16_as_ushort(l3);
    *(ushort4*)(dh + i) = uh;
    *(ushort4*)(dl + i) = ul;
}

// ---------------------------------------------------------------------------
// RoPE + split using the precomputed table.  WHICH 0: Q (folds 1/sqrt(HD)), 1: K.
// ---------------------------------------------------------------------------
template <int WHICH>
__global__ void rope_split_kernel()
{
    const int s = blockIdx.x, h = blockIdx.y, b = blockIdx.z;
    const int d = threadIdx.x;  // 0..63
    const int H = WHICH ? NKVV : NHH;
    const float* P = WHICH ? g_K : g_Q;
    __nv_bfloat16* Dh = WHICH ? g_Kbh : g_Qbh;
    __nv_bfloat16* Dl = WHICH ? g_Kbl : g_Qbl;
    const size_t base = (((size_t)b * H + h) * SS + s) * HDD;

    const double inv = g_invf[d];
    const float f = (float)((double)s * inv);
    float sn, c;
    sincosf(f, &sn, &c);

    const float x1 = P[base + d];
    const float x2 = P[base + d + 64];
    float y1 = x1 * c - x2 * sn;
    float y2 = x2 * c + x1 * sn;
    if (WHICH == 0) { y1 *= 0.08838834764831845f; y2 *= 0.08838834764831845f; }
    __nv_bfloat16 hh, ll;
    split2(y1, hh, ll); Dh[base + d] = hh;      Dl[base + d] = ll;
    split2(y2, hh, ll); Dh[base + d + 64] = hh; Dl[base + d + 64] = ll;
}

// ---------------------------------------------------------------------------
// Shared GEMM structure (bf16 3-term, 128x128 tile, 2-stage) — unchanged R11.
// ---------------------------------------------------------------------------
#define LDP 40
#define XS_ELEM (128 * LDP)                       // 5120
#define STAGE_ELEM (4 * XS_ELEM)                  // 20480
#define GEMM_SMEM (2 * STAGE_ELEM * 2)            // 81920 bytes

__global__ void __launch_bounds__(256, 2) gemm_qkv()
{
    extern __shared__ __align__(16) __nv_bfloat16 sm[];

    const int bx = blockIdx.x;
    const __nv_bfloat16 *Bh_g, *Bl_g;
    int bn, path;   // path 0=Q, 1=K, 2=V
    if (bx < 32)      { Bh_g = g_Wqh; Bl_g = g_Wql; bn = bx * 128;        path = 0; }
    else if (bx < 40) { Bh_g = g_Wkh; Bl_g = g_Wkl; bn = (bx - 32) * 128; path = 1; }
    else              { Bh_g = g_Wvh; Bl_g = g_Wvl; bn = (bx - 40) * 128; path = 2; }

    const __nv_bfloat16* Ah_g = g_hsh;
    const __nv_bfloat16* Al_g = g_hsl;

    const int bm = blockIdx.y * 128;
    const int K = HIDD;
    const int tid = threadIdx.x;
    const int lane = tid & 31;
    const int wid = tid >> 5;
    const int wm = wid & 1;
    const int wn = wid >> 1;

    float acc[4][4][4];
#pragma unroll
    for (int i = 0; i < 4; i++)
#pragma unroll
        for (int j = 0; j < 4; j++)
#pragma unroll
            for (int e = 0; e < 4; e++) acc[i][j][e] = 0.0f;

    const int r0_ = tid >> 2, c0_ = (tid & 3) << 3;
    const int r1_ = (tid + 256) >> 2, c1_ = ((tid + 256) & 3) << 3;

    const int nk = K / 32;

    auto load_stage = [&](int stage, int k0) {
        __nv_bfloat16* Xh = sm + (size_t)stage * STAGE_ELEM;
        __nv_bfloat16* Xl = Xh + XS_ELEM;
        __nv_bfloat16* Wh = Xl + XS_ELEM;
        __nv_bfloat16* Wl = Wh + XS_ELEM;
        cp16(sptr(Xh + r0_ * LDP + c0_), Ah_g + (size_t)(bm + r0_) * K + k0 + c0_);
        cp16(sptr(Xh + r1_ * LDP + c1_), Ah_g + (size_t)(bm + r1_) * K + k0 + c1_);
        cp16(sptr(Xl + r0_ * LDP + c0_), Al_g + (size_t)(bm + r0_) * K + k0 + c0_);
        cp16(sptr(Xl + r1_ * LDP + c1_), Al_g + (size_t)(bm + r1_) * K + k0 + c1_);
        cp16(sptr(Wh + r0_ * LDP + c0_), Bh_g + (size_t)(bn + r0_) * K + k0 + c0_);
        cp16(sptr(Wh + r1_ * LDP + c1_), Bh_g + (size_t)(bn + r1_) * K + k0 + c1_);
        cp16(sptr(Wl + r0_ * LDP + c0_), Bl_g + (size_t)(bn + r0_) * K + k0 + c0_);
        cp16(sptr(Wl + r1_ * LDP + c1_), Bl_g + (size_t)(bn + r1_) * K + k0 + c1_);
        cp_commit();
    };

    load_stage(0, 0);

    const int arow = wm * 64 + (lane & 15);
    const int acol = (lane >> 4) << 3;
    const int brow = wn * 32 + (lane & 7) + ((lane & 16) ? 8 : 0);
    const int bc8  = (lane & 8) ? 8 : 0;

    for (int kt = 0; kt < nk; kt++) {
        const int cur = kt & 1;
        if (kt + 1 < nk) load_stage(cur ^ 1, (kt + 1) * 32);
        if (kt + 1 < nk) cp_wait<1>(); else cp_wait<0>();
        __syncthreads();

        __nv_bfloat16* Xh = sm + (size_t)cur * STAGE_ELEM;
        __nv_bfloat16* Xl = Xh + XS_ELEM;
        __nv_bfloat16* Wh = Xl + XS_ELEM;
        __nv_bfloat16* Wl = Wh + XS_ELEM;

#pragma unroll
        for (int ks = 0; ks < 2; ks++) {
            const int kc = ks * 16;
            uint32_t ah[4][4], al[4][4];
#pragma unroll
            for (int mt = 0; mt < 4; mt++) {
                ldm4(ah[mt], sptr(Xh + (arow + mt * 16) * LDP + kc + acol));
                ldm4(al[mt], sptr(Xl + (arow + mt * 16) * LDP + kc + acol));
            }
            uint32_t bh[4][2], bl[4][2];
            {
                uint32_t t[4];
                ldm4(t, sptr(Wh + brow * LDP + kc + bc8));
                bh[0][0] = t[0]; bh[0][1] = t[1]; bh[1][0] = t[2]; bh[1][1] = t[3];
                ldm4(t, sptr(Wh + (brow + 16) * LDP + kc + bc8));
                bh[2][0] = t[0]; bh[2][1] = t[1]; bh[3][0] = t[2]; bh[3][1] = t[3];
                ldm4(t, sptr(Wl + brow * LDP + kc + bc8));
                bl[0][0] = t[0]; bl[0][1] = t[1]; bl[1][0] = t[2]; bl[1][1] = t[3];
                ldm4(t, sptr(Wl + (brow + 16) * LDP + kc + bc8));
                bl[2][0] = t[0]; bl[2][1] = t[1]; bl[3][0] = t[2]; bl[3][1] = t[3];
            }
#pragma unroll
            for (int mt = 0; mt < 4; mt++)
#pragma unroll
                for (int nt = 0; nt < 4; nt++) {
                    mma_bf16(acc[mt][nt], ah[mt], bh[nt][0], bh[nt][1]);
                    mma_bf16(acc[mt][nt], ah[mt], bl[nt][0], bl[nt][1]);
                    mma_bf16(acc[mt][nt], al[mt], bh[nt][0], bh[nt][1]);
                }
        }
        __syncthreads();
    }

#pragma unroll
    for (int mt = 0; mt < 4; mt++) {
#pragma unroll
        for (int nt = 0; nt < 4; nt++) {
            const int r0 = bm + wm * 64 + mt * 16 + (lane >> 2);
            const int c0 = bn + wn * 32 + nt * 8 + ((lane & 3) << 1);
            const int h0 = c0 / HDD, d0 = c0 % HDD;
            const int b0i = r0 / SS, s0 = r0 % SS;
            const int r1 = r0 + 8;
            const int b1i = r1 / SS, s1 = r1 % SS;
            if (path == 0) {
                float* p0 = g_Q + (((size_t)b0i * NHH + h0) * SS + s0) * HDD + d0;
                *(float2*)p0 = make_float2(acc[mt][nt][0], acc[mt][nt][1]);
                float* p1 = g_Q + (((size_t)b1i * NHH + h0) * SS + s1) * HDD + d0;
                *(float2*)p1 = make_float2(acc[mt][nt][2], acc[mt][nt][3]);
            } else if (path == 1) {
                float* p0 = g_K + (((size_t)b0i * NKVV + h0) * SS + s0) * HDD + d0;
                *(float2*)p0 = make_float2(acc[mt][nt][0], acc[mt][nt][1]);
                float* p1 = g_K + (((size_t)b1i * NKVV + h0) * SS + s1) * HDD + d0;
                *(float2*)p1 = make_float2(acc[mt][nt][2], acc[mt][nt][3]);
            } else {
                const size_t i0 = (((size_t)b0i * NKVV + h0) * SS + s0) * HDD + d0;
                __nv_bfloat16 h_, l_, h2_, l2_;
                split2(acc[mt][nt][0], h_, l_);
                split2(acc[mt][nt][1], h2_, l2_);
                *(__nv_bfloat162*)(g_Vbh + i0) = __halves2bfloat162(h_, h2_);
                *(__nv_bfloat162*)(g_Vbl + i0) = __halves2bfloat162(l_, l2_);
                const size_t i1 = (((size_t)b1i * NKVV + h0) * SS + s1) * HDD + d0;
                split2(acc[mt][nt][2], h_, l_);
                split2(acc[mt][nt][3], h2_, l2_);
                *(__nv_bfloat162*)(g_Vbh + i1) = __halves2bfloat162(h_, h2_);
                *(__nv_bfloat162*)(g_Vbl + i1) = __halves2bfloat162(l_, l2_);
            }
        }
    }
}

__global__ void __launch_bounds__(256, 2) gemm_wo(float* __restrict__ Y)
{
    extern __shared__ __align__(16) __nv_bfloat16 sm[];

    const __nv_bfloat16* Ah_g = g_AOh;
    const __nv_bfloat16* Al_g = g_AOl;
    const __nv_bfloat16* Bh_g = g_Woh;
    const __nv_bfloat16* Bl_g = g_Wol;

    const int bm = blockIdx.y * 128;
    const int bn = blockIdx.x * 128;
    const int K = HIDD, N = HIDD;
    const int tid = threadIdx.x;
    const int lane = tid & 31;
    const int wid = tid >> 5;
    const int wm = wid & 1;
    const int wn = wid >> 1;

    float acc[4][4][4];
#pragma unroll
    for (int i = 0; i < 4; i++)
#pragma unroll
        for (int j = 0; j < 4; j++)
#pragma unroll
            for (int e = 0; e < 4; e++) acc[i][j][e] = 0.0f;

    const int r0_ = tid >> 2, c0_ = (tid & 3) << 3;
    const int r1_ = (tid + 256) >> 2, c1_ = ((tid + 256) & 3) << 3;

    const int nk = K / 32;

    auto load_stage = [&](int stage, int k0) {
        __nv_bfloat16* Xh = sm + (size_t)stage * STAGE_ELEM;
        __nv_bfloat16* Xl = Xh + XS_ELEM;
        __nv_bfloat16* Wh = Xl + XS_ELEM;
        __nv_bfloat16* Wl = Wh + XS_ELEM;
        cp16(sptr(Xh + r0_ * LDP + c0_), Ah_g + (size_t)(bm + r0_) * K + k0 + c0_);
        cp16(sptr(Xh + r1_ * LDP + c1_), Ah_g + (size_t)(bm + r1_) * K + k0 + c1_);
        cp16(sptr(Xl + r0_ * LDP + c0_), Al_g + (size_t)(bm + r0_) * K + k0 + c0_);
        cp16(sptr(Xl + r1_ * LDP + c1_), Al_g + (size_t)(bm + r1_) * K + k0 + c1_);
        cp16(sptr(Wh + r0_ * LDP + c0_), Bh_g + (size_t)(bn + r0_) * K + k0 + c0_);
        cp16(sptr(Wh + r1_ * LDP + c1_), Bh_g + (size_t)(bn + r1_) * K + k0 + c1_);
        cp16(sptr(Wl + r0_ * LDP + c0_), Bl_g + (size_t)(bn + r0_) * K + k0 + c0_);
        cp16(sptr(Wl + r1_ * LDP + c1_), Bl_g + (size_t)(bn + r1_) * K + k0 + c1_);
        cp_commit();
    };

    load_stage(0, 0);

    const int arow = wm * 64 + (lane & 15);
    const int acol = (lane >> 4) << 3;
    const int brow = wn * 32 + (lane & 7) + ((lane & 16) ? 8 : 0);
    const int bc8  = (lane & 8) ? 8 : 0;

    for (int kt = 0; kt < nk; kt++) {
        const int cur = kt & 1;
        if (kt + 1 < nk) load_stage(cur ^ 1, (kt + 1) * 32);
        if (kt + 1 < nk) cp_wait<1>(); else cp_wait<0>();
        __syncthreads();

        __nv_bfloat16* Xh = sm + (size_t)cur * STAGE_ELEM;
        __nv_bfloat16* Xl = Xh + XS_ELEM;
        __nv_bfloat16* Wh = Xl + XS_ELEM;
        __nv_bfloat16* Wl = Wh + XS_ELEM;

#pragma unroll
        for (int ks = 0; ks < 2; ks++) {
            const int kc = ks * 16;
            uint32_t ah[4][4], al[4][4];
#pragma unroll
            for (int mt = 0; mt < 4; mt++) {
                ldm4(ah[mt], sptr(Xh + (arow + mt * 16) * LDP + kc + acol));
                ldm4(al[mt], sptr(Xl + (arow + mt * 16) * LDP + kc + acol));
            }
            uint32_t bh[4][2], bl[4][2];
            {
                uint32_t t[4];
                ldm4(t, sptr(Wh + brow * LDP + kc + bc8));
                bh[0][0] = t[0]; bh[0][1] = t[1]; bh[1][0] = t[2]; bh[1][1] = t[3];
                ldm4(t, sptr(Wh + (brow + 16) * LDP + kc + bc8));
                bh[2][0] = t[0]; bh[2][1] = t[1]; bh[3][0] = t[2]; bh[3][1] = t[3];
                ldm4(t, sptr(Wl + brow * LDP + kc + bc8));
                bl[0][0] = t[0]; bl[0][1] = t[1]; bl[1][0] = t[2]; bl[1][1] = t[3];
                ldm4(t, sptr(Wl + (brow + 16) * LDP + kc + bc8));
                bl[2][0] = t[0]; bl[2][1] = t[1]; bl[3][0] = t[2]; bl[3][1] = t[3];
            }
#pragma unroll
            for (int mt = 0; mt < 4; mt++)
#pragma unroll
                for (int nt = 0; nt < 4; nt++) {
                    mma_bf16(acc[mt][nt], ah[mt], bh[nt][0], bh[nt][1]);
                    mma_bf16(acc[mt][nt], ah[mt], bl[nt][0], bl[nt][1]);
                    mma_bf16(acc[mt][nt], al[mt], bh[nt][0], bh[nt][1]);
                }
        }
        __syncthreads();
    }

#pragma unroll
    for (int mt = 0; mt < 4; mt++) {
#pragma unroll
        for (int nt = 0; nt < 4; nt++) {
            const int r0 = bm + wm * 64 + mt * 16 + (lane >> 2);
            const int c0 = bn + wn * 32 + nt * 8 + ((lane & 3) << 1);
            *(float2*)(Y + (size_t)r0 * N + c0)       = make_float2(acc[mt][nt][0], acc[mt][nt][1]);
            *(float2*)(Y + (size_t)(r0 + 8) * N + c0) = make_float2(acc[mt][nt][2], acc[mt][nt][3]);
        }
    }
}

// ---------------------------------------------------------------------------
// Flash attention (bf16 3-term mma, causal, GQA) with cp.async overlap.
// Separate K and V buffers; V(t) prefetched during QK+softmax, K(t+1)
// prefetched during P-write+PV.  1 CTA/SM (122 KB smem).
// ---------------------------------------------------------------------------
#define LQ 136
#define LP 72

__global__ void __launch_bounds__(256) attn_mma()
{
    extern __shared__ __align__(16) char smraw[];
    __nv_bfloat16* Qh = (__nv_bfloat16*)smraw;        // 64 x LQ
    __nv_bfloat16* Ql = Qh + 64 * LQ;
    __nv_bfloat16* Kh = Ql + 64 * LQ;                 // 64 x LQ
    __nv_bfloat16* Kl = Kh + 64 * LQ;
    __nv_bfloat16* Vh = Kl + 64 * LQ;                 // 64 x LQ
    __nv_bfloat16* Vl = Vh + 64 * LQ;
    __nv_bfloat16* Ph = Vl + 64 * LQ;                 // 64 x LP
    __nv_bfloat16* Pl = Ph + 64 * LP;
    float* row_m     = (float*)(Pl + 64 * LP);
    float* row_l     = row_m + 64;
    float* row_alpha = row_l + 64;
    float* red_max   = row_alpha + 64;   // [2][64]
    float* red_sum   = red_max + 128;    // [2][64]

    const int qt = blockIdx.x, h = blockIdx.y, b = blockIdx.z;
    const int kvh = h >> 2;
    const int tid = threadIdx.x, lane = tid & 31, wid = tid >> 5;
    const int wm = wid & 3, wn = wid >> 2;

    const size_t qoff  = (((size_t)b * NHH + h) * SS + (size_t)qt * 64) * HDD;
    const size_t kvoff = ((size_t)b * NKVV + kvh) * SS * HDD;

    // loader geometry for 64x128 tiles: 1024 16B-chunks per array, 4/thread
    const int lr0 = tid >> 2,  lc0 = (tid & 3) << 5;          // unused pattern; use j-loop

    auto issue_K = [&](int kv0) {
#pragma unroll
        for (int j = 0; j < 4; j++) {
            const int i = tid + j * 256;
            const int r = i >> 4, c = (i & 15) << 3;
            const size_t go = kvoff + (size_t)(kv0 + r) * HDD + c;
            cp16(sptr(Kh + r * LQ + c), g_Kbh + go);
            cp16(sptr(Kl + r * LQ + c), g_Kbl + go);
        }
        cp_commit();
    };
    auto issue_V = [&](int kv0) {
#pragma unroll
        for (int j = 0; j < 4; j++) {
            const int i = tid + j * 256;
            const int r = i >> 4, c = (i & 15) << 3;
            const size_t go = kvoff + (size_t)(kv0 + r) * HDD + c;
            cp16(sptr(Vh + r * LQ + c), g_Vbh + go);
            cp16(sptr(Vl + r * LQ + c), g_Vbl + go);
        }
        cp_commit();
    };

    // Prefetch K(0) before the (synchronous) Q load — overlaps them.
    issue_K(0);

    // Load Q tile 64x128 hi/lo
#pragma unroll
    for (int j = 0; j < 4; j++) {
        const int i = tid + j * 256;
        const int r = i >> 4, c = (i & 15) << 3;
        *(uint4*)&Qh[r * LQ + c] = *(const uint4*)(g_Qbh + qoff + (size_t)r * HDD + c);
        *(uint4*)&Ql[r * LQ + c] = *(const uint4*)(g_Qbl + qoff + (size_t)r * HDD + c);
    }
    if (tid < 64) { row_m[tid] = -1e30f; row_l[tid] = 0.0f; }

    float O[8][4];
#pragma unroll
    for (int i = 0; i < 8; i++)
#pragma unroll
        for (int e = 0; e < 4; e++) O[i][e] = 0.0f;

    const int ntiles = qt + 1;

    const int ar   = wm * 16 + (lane & 15);
    const int ac   = (lane >> 4) << 3;
    const int brr  = (lane & 7) + ((lane & 16) ? 8 : 0);
    const int bc8  = (lane & 8) ? 8 : 0;
    const int par  = wm * 16 + (lane & 15);
    const int vr   = (lane & 7) + ((lane & 8) ? 8 : 0);
    const int vc8  = (lane & 16) ? 8 : 0;
    const int rloc = wm * 16 + (lane >> 2);

    for (int t = 0; t < ntiles; t++) {
        const int kv0 = t * 64;

        // K(t) ready; also guarantees previous PV finished (V buffer free)
        cp_wait<0>();
        __syncthreads();                               // [1]

        // Prefetch V(t): overlaps QK + softmax
        issue_V(kv0);

        // ---- QK^T: 16 rows x 32 kv per warp ----
        float sc[4][4];
#pragma unroll
        for (int nt = 0; nt < 4; nt++)
#pragma unroll
            for (int e = 0; e < 4; e++) sc[nt][e] = 0.0f;

#pragma unroll
        for (int ks = 0; ks < 8; ks++) {
            uint32_t aq[4], aql[4], bkA[4], bkB[4], bklA[4], bklB[4];
            ldm4(aq,   sptr(Qh + ar * LQ + ks * 16 + ac));
            ldm4(aql,  sptr(Ql + ar * LQ + ks * 16 + ac));
            ldm4(bkA,  sptr(Kh + (wn * 32 + brr)      * LQ + ks * 16 + bc8));
            ldm4(bkB,  sptr(Kh + (wn * 32 + 16 + brr) * LQ + ks * 16 + bc8));
            ldm4(bklA, sptr(Kl + (wn * 32 + brr)      * LQ + ks * 16 + bc8));
            ldm4(bklB, sptr(Kl + (wn * 32 + 16 + brr) * LQ + ks * 16 + bc8));
            mma_bf16(sc[0], aq,  bkA[0],  bkA[1]);
            mma_bf16(sc[1], aq,  bkA[2],  bkA[3]);
            mma_bf16(sc[2], aq,  bkB[0],  bkB[1]);
            mma_bf16(sc[3], aq,  bkB[2],  bkB[3]);
            mma_bf16(sc[0], aq,  bklA[0], bklA[1]);
            mma_bf16(sc[1], aq,  bklA[2], bklA[3]);
            mma_bf16(sc[2], aq,  bklB[0], bklB[1]);
            mma_bf16(sc[3], aq,  bklB[2], bklB[3]);
            mma_bf16(sc[0], aql, bkA[0],  bkA[1]);
            mma_bf16(sc[1], aql, bkA[2],  bkA[3]);
            mma_bf16(sc[2], aql, bkB[0],  bkB[1]);
            mma_bf16(sc[3], aql, bkB[2],  bkB[3]);
        }

        // ---- causal mask (Q pre-scaled) ----
        const int grow = qt * 64 + rloc;
        const int gcol = kv0 + wn * 32 + ((lane & 3) << 1);
#pragma unroll
        for (int nt = 0; nt < 4; nt++)
#pragma unroll
            for (int e = 0; e < 4; e++) {
                const int rr = grow + ((e & 2) ? 8 : 0);
                const int cc = gcol + nt * 8 + (e & 1);
                sc[nt][e] = (cc <= rr) ? sc[nt][e] : -1e30f;
            }

        // ---- row max ----
        float m0 = -1e30f, m1 = -1e30f;
#pragma unroll
        for (int nt = 0; nt < 4; nt++) {
            m0 = fmaxf(m0, fmaxf(sc[nt][0], sc[nt][1]));
            m1 = fmaxf(m1, fmaxf(sc[nt][2], sc[nt][3]));
        }
        m0 = fmaxf(m0, __shfl_xor_sync(0xffffffffu, m0, 1));
        m0 = fmaxf(m0, __shfl_xor_sync(0xffffffffu, m0, 2));
        m1 = fmaxf(m1, __shfl_xor_sync(0xffffffffu, m1, 1));
        m1 = fmaxf(m1, __shfl_xor_sync(0xffffffffu, m1, 2));
        if ((lane & 3) == 0) {
            red_max[wn * 64 + rloc]     = m0;
            red_max[wn * 64 + rloc + 8] = m1;
        }
        __syncthreads();                               // [3] all warps past QK (K free)

        // Prefetch K(t+1): overlaps softmax tail + P write + PV
        if (t + 1 < ntiles) issue_K(kv0 + 64);

        if (tid < 64) {
            const float mo = row_m[tid];
            const float mn = fmaxf(mo, fmaxf(red_max[tid], red_max[64 + tid]));
            row_alpha[tid] = __expf(mo - mn);
            row_m[tid] = mn;
        }
        __syncthreads();                               // [4]

        // ---- P = exp(s-m), split to smem, partial sums ----
        const float mr0 = row_m[rloc];
        const float mr1 = row_m[rloc + 8];
        float s0 = 0.0f, s1 = 0.0f;
#pragma unroll
        for (int nt = 0; nt < 4; nt++) {
            const float p0 = __expf(sc[nt][0] - mr0);
            const float p1 = __expf(sc[nt][1] - mr0);
            const float p2 = __expf(sc[nt][2] - mr1);
            const float p3 = __expf(sc[nt][3] - mr1);
            s0 += p0 + p1; s1 += p2 + p3;
            const int pc = wn * 32 + nt * 8 + ((lane & 3) << 1);
            __nv_bfloat16 h0, l0, h1, l1;
            split2(p0, h0, l0); split2(p1, h1, l1);
            *(__nv_bfloat162*)(Ph + rloc * LP + pc) = __halves2bfloat162(h0, h1);
            *(__nv_bfloat162*)(Pl + rloc * LP + pc) = __halves2bfloat162(l0, l1);
            split2(p2, h0, l0); split2(p3, h1, l1);
            *(__nv_bfloat162*)(Ph + (rloc + 8) * LP + pc) = __halves2bfloat162(h0, h1);
            *(__nv_bfloat162*)(Pl + (rloc + 8) * LP + pc) = __halves2bfloat162(l0, l1);
        }
        s0 += __shfl_xor_sync(0xffffffffu, s0, 1);
        s0 += __shfl_xor_sync(0xffffffffu, s0, 2);
        s1 += __shfl_xor_sync(0xffffffffu, s1, 1);
        s1 += __shfl_xor_sync(0xffffffffu, s1, 2);
        if ((lane & 3) == 0) {
            red_sum[wn * 64 + rloc]     = s0;
            red_sum[wn * 64 + rloc + 8] = s1;
        }
        __syncthreads();                               // [5] P visible
        if (tid < 64)
            row_l[tid] = row_l[tid] * row_alpha[tid] + red_sum[tid] + red_sum[64 + tid];

        // Wait V(t) only (K(t+1) may still be in flight)
        if (t + 1 < ntiles) cp_wait<1>(); else cp_wait<0>();
        __syncthreads();                               // [6]

        // ---- rescale O, PV ----
        const float a0 = row_alpha[rloc];
        const float a1 = row_alpha[rloc + 8];
#pragma unroll
        for (int nt = 0; nt < 8; nt++) {
            O[nt][0] *= a0; O[nt][1] *= a0; O[nt][2] *= a1; O[nt][3] *= a1;
        }
#pragma unroll
        for (int ks = 0; ks < 4; ks++) {
            uint32_t ap[4], apl[4];
            ldm4(ap,  sptr(Ph + par * LP + ks * 16 + ac));
            ldm4(apl, sptr(Pl + par * LP + ks * 16 + ac));
#pragma unroll
            for (int g = 0; g < 4; g++) {
                uint32_t bv[4], bvl[4];
                ldm4t(bv,  sptr(Vh + (ks * 16 + vr) * LQ + wn * 64 + g * 16 + vc8));
                ldm4t(bvl, sptr(Vl + (ks * 16 + vr) * LQ + wn * 64 + g * 16 + vc8));
                mma_bf16(O[g * 2 + 0], ap,  bv[0],  bv[1]);
                mma_bf16(O[g * 2 + 1], ap,  bv[2],  bv[3]);
                mma_bf16(O[g * 2 + 0], ap,  bvl[0], bvl[1]);
                mma_bf16(O[g * 2 + 1], ap,  bvl[2], bvl[3]);
                mma_bf16(O[g * 2 + 0], apl, bv[0],  bv[1]);
                mma_bf16(O[g * 2 + 1], apl, bv[2],  bv[3]);
            }
        }
    }

    __syncthreads();
    const float inv0 = 1.0f / row_l[rloc];
    const float inv1 = 1.0f / row_l[rloc + 8];
    const size_t ao = ((size_t)b * SS + (size_t)qt * 64) * HIDD + (size_t)h * HDD;
#pragma unroll
    for (int nt = 0; nt < 8; nt++) {
        const int cc = wn * 64 + nt * 8 + ((lane & 3) << 1);
        __nv_bfloat16 h0, l0, h1, l1;
        split2(O[nt][0] * inv0, h0, l0); split2(O[nt][1] * inv0, h1, l1);
        *(__nv_bfloat162*)(g_AOh + ao + (size_t)rloc * HIDD + cc) = __halves2bfloat162(h0, h1);
        *(__nv_bfloat162*)(g_AOl + ao + (size_t)rloc * HIDD + cc) = __halves2bfloat162(l0, l1);
        split2(O[nt][2] * inv1, h0, l0); split2(O[nt][3] * inv1, h1, l1);
        *(__nv_bfloat162*)(g_AOh + ao + (size_t)(rloc + 8) * HIDD + cc) = __halves2bfloat162(h0, h1);
        *(__nv_bfloat162*)(g_AOl + ao + (size_t)(rloc + 8) * HIDD + cc) = __halves2bfloat162(l0, l1);
    }
}

// ---------------------------------------------------------------------------
extern "C" void kernel_launch(void* const* d_in, const int* in_sizes, int n_in,
                              void* d_out, int out_size)
{
    (void)in_sizes; (void)n_in; (void)out_size;
    const float* hs = (const float*)d_in[0];
    const float* Wq = (const float*)d_in[1];
    const float* Wk = (const float*)d_in[2];
    const float* Wv = (const float*)d_in[3];
    const float* Wo = (const float*)d_in[4];
    float* out = (float*)d_out;

    const int M = BB * SS;  // 4096
    dim3 blk(256);

    const int attn_smem =
        (64 * LQ * 6 + 64 * LP * 2) * (int)sizeof(__nv_bfloat16) +
        (64 * 3 + 128 * 2) * (int)sizeof(float);
    cudaFuncSetAttribute(attn_mma, cudaFuncAttributeMaxDynamicSharedMemorySize, attn_smem);
    cudaFuncSetAttribute(gemm_qkv, cudaFuncAttributeMaxDynamicSharedMemorySize, GEMM_SMEM);
    cudaFuncSetAttribute(gemm_wo,  cudaFuncAttributeMaxDynamicSharedMemorySize, GEMM_SMEM);

    // RoPE table + input splits
    invf_kernel<<<1, 64>>>();
    split_kernel<<<(unsigned)(N_HS / 1024), blk>>>(hs, 0, N_HS);
    split_kernel<<<(unsigned)(N_WQ / 1024), blk>>>(Wq, 1, N_WQ);
    split_kernel<<<(unsigned)(N_WK / 1024), blk>>>(Wk, 2, N_WK);
    split_kernel<<<(unsigned)(N_WK / 1024), blk>>>(Wv, 3, N_WK);
    split_kernel<<<(unsigned)(N_WQ / 1024), blk>>>(Wo, 4, N_WQ);

    // Fused Q+K+V projections (one launch, 48x32 blocks)
    gemm_qkv<<<dim3(48, M / 128), blk, GEMM_SMEM>>>();

    // RoPE + split for Q/K
    rope_split_kernel<0><<<dim3(SS, NHH, BB), 64>>>();
    rope_split_kernel<1><<<dim3(SS, NKVV, BB), 64>>>();

    // Causal GQA flash attention -> g_AOh/g_AOl
    attn_mma<<<dim3(SS / 64, NHH, BB), blk, attn_smem>>>();

    // Output projection
    gemm_wo<<<dim3(HIDD / 128, M / 128), blk, GEMM_SMEM>>>(out);
}

// round 14
// speedup vs baseline: 1.0186x; 1.0186x over previous
#include <cuda_runtime.h>
#include <cuda_bf16.h>
#include <math.h>
#include <stdint.h>

// Problem constants
#define BB   2
#define SS   2048
#define HIDD 4096
#define NHH  32
#define NKVV 8
#define HDD  128
#define GG   4

#define N_HS ((size_t)BB * SS * HIDD)
#define N_WQ ((size_t)HIDD * HIDD)
#define N_WK ((size_t)NKVV * HDD * HIDD)
#define N_QB ((size_t)BB * NHH * SS * HDD)
#define N_KB ((size_t)BB * NKVV * SS * HDD)

// fp32 intermediates (pre-RoPE)
__device__ float g_Q[N_QB];
__device__ float g_K[N_KB];

// RoPE inverse-frequency table (double, precomputed once)
__device__ double g_invf[64];

// bf16 hi/lo split operands
__device__ __nv_bfloat16 g_hsh[N_HS],  g_hsl[N_HS];
__device__ __nv_bfloat16 g_Wqh[N_WQ],  g_Wql[N_WQ];
__device__ __nv_bfloat16 g_Wkh[N_WK],  g_Wkl[N_WK];
__device__ __nv_bfloat16 g_Wvh[N_WK],  g_Wvl[N_WK];
__device__ __nv_bfloat16 g_Woh[N_WQ],  g_Wol[N_WQ];
__device__ __nv_bfloat16 g_Qbh[N_QB],  g_Qbl[N_QB];   // post-RoPE, pre-scaled
__device__ __nv_bfloat16 g_Kbh[N_KB],  g_Kbl[N_KB];   // post-RoPE
__device__ __nv_bfloat16 g_Vbh[N_KB],  g_Vbl[N_KB];   // written by fused QKV GEMM
__device__ __nv_bfloat16 g_AOh[N_HS],  g_AOl[N_HS];   // attention output

// ---------------------------------------------------------------------------
// helpers
// ---------------------------------------------------------------------------
__device__ __forceinline__ uint32_t sptr(const void* p) {
    return (uint32_t)__cvta_generic_to_shared(p);
}
__device__ __forceinline__ void cp16(uint32_t d, const void* s) {
    asm volatile("cp.async.cg.shared.global [%0], [%1], 16;\n" :: "r"(d), "l"(s));
}
__device__ __forceinline__ void cp_commit() { asm volatile("cp.async.commit_group;\n"); }
template <int N> __device__ __forceinline__ void cp_wait() {
    asm volatile("cp.async.wait_group %0;\n" :: "n"(N));
}
__device__ __forceinline__ void ldm4(uint32_t* r, uint32_t a) {
    asm volatile("ldmatrix.sync.aligned.m8n8.x4.shared.b16 {%0,%1,%2,%3}, [%4];\n"
        : "=r"(r[0]), "=r"(r[1]), "=r"(r[2]), "=r"(r[3]) : "r"(a));
}
__device__ __forceinline__ void ldm4t(uint32_t* r, uint32_t a) {
    asm volatile("ldmatrix.sync.aligned.m8n8.x4.trans.shared.b16 {%0,%1,%2,%3}, [%4];\n"
        : "=r"(r[0]), "=r"(r[1]), "=r"(r[2]), "=r"(r[3]) : "r"(a));
}
__device__ __forceinline__ void mma_bf16(float* c, const uint32_t* a, uint32_t b0, uint32_t b1) {
    asm volatile(
        "mma.sync.aligned.m16n8k16.row.col.f32.bf16.bf16.f32 "
        "{%0,%1,%2,%3}, {%4,%5,%6,%7}, {%8,%9}, {%0,%1,%2,%3};\n"
        : "+f"(c[0]), "+f"(c[1]), "+f"(c[2]), "+f"(c[3])
        : "r"(a[0]), "r"(a[1]), "r"(a[2]), "r"(a[3]), "r"(b0), "r"(b1));
}
__device__ __forceinline__ void split2(float x, __nv_bfloat16& h, __nv_bfloat16& l) {
    h = __float2bfloat16(x);
    l = __float2bfloat16(x - __bfloat162float(h));
}

// ---------------------------------------------------------------------------
// Precompute inv-freq table (same expression -> bit-identical phases)
// ---------------------------------------------------------------------------
__global__ void invf_kernel()
{
    const int d = threadIdx.x;  // 0..63
    g_invf[d] = pow(10000.0, -(double)d / 64.0);
}

// ---------------------------------------------------------------------------
// Elementwise fp32 -> bf16 hi/lo split (inputs only).
// ---------------------------------------------------------------------------
__global__ void __launch_bounds__(256) split_kernel(const float* __restrict__ src,
                                                    int dsel, size_t n)
{
    __nv_bfloat16 *dh, *dl;
    switch (dsel) {
        case 1: dh = g_Wqh; dl = g_Wql; break;
        case 2: dh = g_Wkh; dl = g_Wkl; break;
        case 3: dh = g_Wvh; dl = g_Wvl; break;
        case 4: dh = g_Woh; dl = g_Wol; break;
        default: dh = g_hsh; dl = g_hsl; break;
    }
    const size_t i = ((size_t)blockIdx.x * 256 + threadIdx.x) * 4;
    if (i >= n) return;
    float4 v = *(const float4*)(src + i);
    __nv_bfloat16 h0, l0, h1, l1, h2, l2, h3, l3;
    split2(v.x, h0, l0); split2(v.y, h1, l1);
    split2(v.z, h2, l2); split2(v.w, h3, l3);
    ushort4 uh, ul;
    uh.x = __bfloat16_as_ushort(h0); uh.y = __bfloat16_as_ushort(h1);
    uh.z = __bfloat16_as_ushort(h2); uh.w = __bfloat16_as_ushort(h3);
    ul.x = __bfloat16_as_ushort(l0); ul.y = __bfloat16_as_ushort(l1);
    ul.z = __bfloat16_as_ushort(l2); ul.w = __bfloat16_as_ushort(l3);
    *(ushort4*)(dh + i) = uh;
    *(ushort4*)(dl + i) = ul;
}

// ---------------------------------------------------------------------------
// RoPE + split using the precomputed table.  WHICH 0: Q (folds 1/sqrt(HD)), 1: K.
// ---------------------------------------------------------------------------
template <int WHICH>
__global__ void rope_split_kernel()
{
    const int s = blockIdx.x, h = blockIdx.y, b = blockIdx.z;
    const int d = threadIdx.x;  // 0..63
    const int H = WHICH ? NKVV : NHH;
    const float* P = WHICH ? g_K : g_Q;
    __nv_bfloat16* Dh = WHICH ? g_Kbh : g_Qbh;
    __nv_bfloat16* Dl = WHICH ? g_Kbl : g_Qbl;
    const size_t base = (((size_t)b * H + h) * SS + s) * HDD;

    const double inv = g_invf[d];
    const float f = (float)((double)s * inv);
    float sn, c;
    sincosf(f, &sn, &c);

    const float x1 = P[base + d];
    const float x2 = P[base + d + 64];
    float y1 = x1 * c - x2 * sn;
    float y2 = x2 * c + x1 * sn;
    if (WHICH == 0) { y1 *= 0.08838834764831845f; y2 *= 0.08838834764831845f; }
    __nv_bfloat16 hh, ll;
    split2(y1, hh, ll); Dh[base + d] = hh;      Dl[base + d] = ll;
    split2(y2, hh, ll); Dh[base + d + 64] = hh; Dl[base + d + 64] = ll;
}

// ---------------------------------------------------------------------------
// Shared GEMM structure (bf16 3-term, 128x128 tile, 2-stage) — unchanged R11.
// ---------------------------------------------------------------------------
#define LDP 40
#define XS_ELEM (128 * LDP)                       // 5120
#define STAGE_ELEM (4 * XS_ELEM)                  // 20480
#define GEMM_SMEM (2 * STAGE_ELEM * 2)            // 81920 bytes

__global__ void __launch_bounds__(256, 2) gemm_qkv()
{
    extern __shared__ __align__(16) __nv_bfloat16 sm[];

    const int bx = blockIdx.x;
    const __nv_bfloat16 *Bh_g, *Bl_g;
    int bn, path;   // path 0=Q, 1=K, 2=V
    if (bx < 32)      { Bh_g = g_Wqh; Bl_g = g_Wql; bn = bx * 128;        path = 0; }
    else if (bx < 40) { Bh_g = g_Wkh; Bl_g = g_Wkl; bn = (bx - 32) * 128; path = 1; }
    else              { Bh_g = g_Wvh; Bl_g = g_Wvl; bn = (bx - 40) * 128; path = 2; }

    const __nv_bfloat16* Ah_g = g_hsh;
    const __nv_bfloat16* Al_g = g_hsl;

    const int bm = blockIdx.y * 128;
    const int K = HIDD;
    const int tid = threadIdx.x;
    const int lane = tid & 31;
    const int wid = tid >> 5;
    const int wm = wid & 1;
    const int wn = wid >> 1;

    float acc[4][4][4];
#pragma unroll
    for (int i = 0; i < 4; i++)
#pragma unroll
        for (int j = 0; j < 4; j++)
#pragma unroll
            for (int e = 0; e < 4; e++) acc[i][j][e] = 0.0f;

    const int r0_ = tid >> 2, c0_ = (tid & 3) << 3;
    const int r1_ = (tid + 256) >> 2, c1_ = ((tid + 256) & 3) << 3;

    const int nk = K / 32;

    auto load_stage = [&](int stage, int k0) {
        __nv_bfloat16* Xh = sm + (size_t)stage * STAGE_ELEM;
        __nv_bfloat16* Xl = Xh + XS_ELEM;
        __nv_bfloat16* Wh = Xl + XS_ELEM;
        __nv_bfloat16* Wl = Wh + XS_ELEM;
        cp16(sptr(Xh + r0_ * LDP + c0_), Ah_g + (size_t)(bm + r0_) * K + k0 + c0_);
        cp16(sptr(Xh + r1_ * LDP + c1_), Ah_g + (size_t)(bm + r1_) * K + k0 + c1_);
        cp16(sptr(Xl + r0_ * LDP + c0_), Al_g + (size_t)(bm + r0_) * K + k0 + c0_);
        cp16(sptr(Xl + r1_ * LDP + c1_), Al_g + (size_t)(bm + r1_) * K + k0 + c1_);
        cp16(sptr(Wh + r0_ * LDP + c0_), Bh_g + (size_t)(bn + r0_) * K + k0 + c0_);
        cp16(sptr(Wh + r1_ * LDP + c1_), Bh_g + (size_t)(bn + r1_) * K + k0 + c1_);
        cp16(sptr(Wl + r0_ * LDP + c0_), Bl_g + (size_t)(bn + r0_) * K + k0 + c0_);
        cp16(sptr(Wl + r1_ * LDP + c1_), Bl_g + (size_t)(bn + r1_) * K + k0 + c1_);
        cp_commit();
    };

    load_stage(0, 0);

    const int arow = wm * 64 + (lane & 15);
    const int acol = (lane >> 4) << 3;
    const int brow = wn * 32 + (lane & 7) + ((lane & 16) ? 8 : 0);
    const int bc8  = (lane & 8) ? 8 : 0;

    for (int kt = 0; kt < nk; kt++) {
        const int cur = kt & 1;
        if (kt + 1 < nk) load_stage(cur ^ 1, (kt + 1) * 32);
        if (kt + 1 < nk) cp_wait<1>(); else cp_wait<0>();
        __syncthreads();

        __nv_bfloat16* Xh = sm + (size_t)cur * STAGE_ELEM;
        __nv_bfloat16* Xl = Xh + XS_ELEM;
        __nv_bfloat16* Wh = Xl + XS_ELEM;
        __nv_bfloat16* Wl = Wh + XS_ELEM;

#pragma unroll
        for (int ks = 0; ks < 2; ks++) {
            const int kc = ks * 16;
            uint32_t ah[4][4], al[4][4];
#pragma unroll
            for (int mt = 0; mt < 4; mt++) {
                ldm4(ah[mt], sptr(Xh + (arow + mt * 16) * LDP + kc + acol));
                ldm4(al[mt], sptr(Xl + (arow + mt * 16) * LDP + kc + acol));
            }
            uint32_t bh[4][2], bl[4][2];
            {
                uint32_t t[4];
                ldm4(t, sptr(Wh + brow * LDP + kc + bc8));
                bh[0][0] = t[0]; bh[0][1] = t[1]; bh[1][0] = t[2]; bh[1][1] = t[3];
                ldm4(t, sptr(Wh + (brow + 16) * LDP + kc + bc8));
                bh[2][0] = t[0]; bh[2][1] = t[1]; bh[3][0] = t[2]; bh[3][1] = t[3];
                ldm4(t, sptr(Wl + brow * LDP + kc + bc8));
                bl[0][0] = t[0]; bl[0][1] = t[1]; bl[1][0] = t[2]; bl[1][1] = t[3];
                ldm4(t, sptr(Wl + (brow + 16) * LDP + kc + bc8));
                bl[2][0] = t[0]; bl[2][1] = t[1]; bl[3][0] = t[2]; bl[3][1] = t[3];
            }
#pragma unroll
            for (int mt = 0; mt < 4; mt++)
#pragma unroll
                for (int nt = 0; nt < 4; nt++) {
                    mma_bf16(acc[mt][nt], ah[mt], bh[nt][0], bh[nt][1]);
                    mma_bf16(acc[mt][nt], ah[mt], bl[nt][0], bl[nt][1]);
                    mma_bf16(acc[mt][nt], al[mt], bh[nt][0], bh[nt][1]);
                }
        }
        __syncthreads();
    }

#pragma unroll
    for (int mt = 0; mt < 4; mt++) {
#pragma unroll
        for (int nt = 0; nt < 4; nt++) {
            const int r0 = bm + wm * 64 + mt * 16 + (lane >> 2);
            const int c0 = bn + wn * 32 + nt * 8 + ((lane & 3) << 1);
            const int h0 = c0 / HDD, d0 = c0 % HDD;
            const int b0i = r0 / SS, s0 = r0 % SS;
            const int r1 = r0 + 8;
            const int b1i = r1 / SS, s1 = r1 % SS;
            if (path == 0) {
                float* p0 = g_Q + (((size_t)b0i * NHH + h0) * SS + s0) * HDD + d0;
                *(float2*)p0 = make_float2(acc[mt][nt][0], acc[mt][nt][1]);
                float* p1 = g_Q + (((size_t)b1i * NHH + h0) * SS + s1) * HDD + d0;
                *(float2*)p1 = make_float2(acc[mt][nt][2], acc[mt][nt][3]);
            } else if (path == 1) {
                float* p0 = g_K + (((size_t)b0i * NKVV + h0) * SS + s0) * HDD + d0;
                *(float2*)p0 = make_float2(acc[mt][nt][0], acc[mt][nt][1]);
                float* p1 = g_K + (((size_t)b1i * NKVV + h0) * SS + s1) * HDD + d0;
                *(float2*)p1 = make_float2(acc[mt][nt][2], acc[mt][nt][3]);
            } else {
                const size_t i0 = (((size_t)b0i * NKVV + h0) * SS + s0) * HDD + d0;
                __nv_bfloat16 h_, l_, h2_, l2_;
                split2(acc[mt][nt][0], h_, l_);
                split2(acc[mt][nt][1], h2_, l2_);
                *(__nv_bfloat162*)(g_Vbh + i0) = __halves2bfloat162(h_, h2_);
                *(__nv_bfloat162*)(g_Vbl + i0) = __halves2bfloat162(l_, l2_);
                const size_t i1 = (((size_t)b1i * NKVV + h0) * SS + s1) * HDD + d0;
                split2(acc[mt][nt][2], h_, l_);
                split2(acc[mt][nt][3], h2_, l2_);
                *(__nv_bfloat162*)(g_Vbh + i1) = __halves2bfloat162(h_, h2_);
                *(__nv_bfloat162*)(g_Vbl + i1) = __halves2bfloat162(l_, l2_);
            }
        }
    }
}

__global__ void __launch_bounds__(256, 2) gemm_wo(float* __restrict__ Y)
{
    extern __shared__ __align__(16) __nv_bfloat16 sm[];

    const __nv_bfloat16* Ah_g = g_AOh;
    const __nv_bfloat16* Al_g = g_AOl;
    const __nv_bfloat16* Bh_g = g_Woh;
    const __nv_bfloat16* Bl_g = g_Wol;

    const int bm = blockIdx.y * 128;
    const int bn = blockIdx.x * 128;
    const int K = HIDD, N = HIDD;
    const int tid = threadIdx.x;
    const int lane = tid & 31;
    const int wid = tid >> 5;
    const int wm = wid & 1;
    const int wn = wid >> 1;

    float acc[4][4][4];
#pragma unroll
    for (int i = 0; i < 4; i++)
#pragma unroll
        for (int j = 0; j < 4; j++)
#pragma unroll
            for (int e = 0; e < 4; e++) acc[i][j][e] = 0.0f;

    const int r0_ = tid >> 2, c0_ = (tid & 3) << 3;
    const int r1_ = (tid + 256) >> 2, c1_ = ((tid + 256) & 3) << 3;

    const int nk = K / 32;

    auto load_stage = [&](int stage, int k0) {
        __nv_bfloat16* Xh = sm + (size_t)stage * STAGE_ELEM;
        __nv_bfloat16* Xl = Xh + XS_ELEM;
        __nv_bfloat16* Wh = Xl + XS_ELEM;
        __nv_bfloat16* Wl = Wh + XS_ELEM;
        cp16(sptr(Xh + r0_ * LDP + c0_), Ah_g + (size_t)(bm + r0_) * K + k0 + c0_);
        cp16(sptr(Xh + r1_ * LDP + c1_), Ah_g + (size_t)(bm + r1_) * K + k0 + c1_);
        cp16(sptr(Xl + r0_ * LDP + c0_), Al_g + (size_t)(bm + r0_) * K + k0 + c0_);
        cp16(sptr(Xl + r1_ * LDP + c1_), Al_g + (size_t)(bm + r1_) * K + k0 + c1_);
        cp16(sptr(Wh + r0_ * LDP + c0_), Bh_g + (size_t)(bn + r0_) * K + k0 + c0_);
        cp16(sptr(Wh + r1_ * LDP + c1_), Bh_g + (size_t)(bn + r1_) * K + k0 + c1_);
        cp16(sptr(Wl + r0_ * LDP + c0_), Bl_g + (size_t)(bn + r0_) * K + k0 + c0_);
        cp16(sptr(Wl + r1_ * LDP + c1_), Bl_g + (size_t)(bn + r1_) * K + k0 + c1_);
        cp_commit();
    };

    load_stage(0, 0);

    const int arow = wm * 64 + (lane & 15);
    const int acol = (lane >> 4) << 3;
    const int brow = wn * 32 + (lane & 7) + ((lane & 16) ? 8 : 0);
    const int bc8  = (lane & 8) ? 8 : 0;

    for (int kt = 0; kt < nk; kt++) {
        const int cur = kt & 1;
        if (kt + 1 < nk) load_stage(cur ^ 1, (kt + 1) * 32);
        if (kt + 1 < nk) cp_wait<1>(); else cp_wait<0>();
        __syncthreads();

        __nv_bfloat16* Xh = sm + (size_t)cur * STAGE_ELEM;
        __nv_bfloat16* Xl = Xh + XS_ELEM;
        __nv_bfloat16* Wh = Xl + XS_ELEM;
        __nv_bfloat16* Wl = Wh + XS_ELEM;

#pragma unroll
        for (int ks = 0; ks < 2; ks++) {
            const int kc = ks * 16;
            uint32_t ah[4][4], al[4][4];
#pragma unroll
            for (int mt = 0; mt < 4; mt++) {
                ldm4(ah[mt], sptr(Xh + (arow + mt * 16) * LDP + kc + acol));
                ldm4(al[mt], sptr(Xl + (arow + mt * 16) * LDP + kc + acol));
            }
            uint32_t bh[4][2], bl[4][2];
            {
                uint32_t t[4];
                ldm4(t, sptr(Wh + brow * LDP + kc + bc8));
                bh[0][0] = t[0]; bh[0][1] = t[1]; bh[1][0] = t[2]; bh[1][1] = t[3];
                ldm4(t, sptr(Wh + (brow + 16) * LDP + kc + bc8));
                bh[2][0] = t[0]; bh[2][1] = t[1]; bh[3][0] = t[2]; bh[3][1] = t[3];
                ldm4(t, sptr(Wl + brow * LDP + kc + bc8));
                bl[0][0] = t[0]; bl[0][1] = t[1]; bl[1][0] = t[2]; bl[1][1] = t[3];
                ldm4(t, sptr(Wl + (brow + 16) * LDP + kc + bc8));
                bl[2][0] = t[0]; bl[2][1] = t[1]; bl[3][0] = t[2]; bl[3][1] = t[3];
            }
#pragma unroll
            for (int mt = 0; mt < 4; mt++)
#pragma unroll
                for (int nt = 0; nt < 4; nt++) {
                    mma_bf16(acc[mt][nt], ah[mt], bh[nt][0], bh[nt][1]);
                    mma_bf16(acc[mt][nt], ah[mt], bl[nt][0], bl[nt][1]);
                    mma_bf16(acc[mt][nt], al[mt], bh[nt][0], bh[nt][1]);
                }
        }
        __syncthreads();
    }

#pragma unroll
    for (int mt = 0; mt < 4; mt++) {
#pragma unroll
        for (int nt = 0; nt < 4; nt++) {
            const int r0 = bm + wm * 64 + mt * 16 + (lane >> 2);
            const int c0 = bn + wn * 32 + nt * 8 + ((lane & 3) << 1);
            *(float2*)(Y + (size_t)r0 * N + c0)       = make_float2(acc[mt][nt][0], acc[mt][nt][1]);
            *(float2*)(Y + (size_t)(r0 + 8) * N + c0) = make_float2(acc[mt][nt][2], acc[mt][nt][3]);
        }
    }
}

// ---------------------------------------------------------------------------
// Flash attention: shared K/V smem buffer (2 CTAs/SM) + async V prefetch.
// V(t) issued via cp.async right after the max-reduce barrier (K reads done),
// waited just before PV.  Heavy qt tiles launch first (reverse mapping).
// ---------------------------------------------------------------------------
#define LQ 136
#define LP 72

__global__ void __launch_bounds__(256) attn_mma()
{
    extern __shared__ __align__(16) char smraw[];
    __nv_bfloat16* Qh  = (__nv_bfloat16*)smraw;        // 64 x LQ
    __nv_bfloat16* Ql  = Qh + 64 * LQ;
    __nv_bfloat16* KVh = Ql + 64 * LQ;                 // 64 x LQ (K then V)
    __nv_bfloat16* KVl = KVh + 64 * LQ;
    __nv_bfloat16* Ph  = KVl + 64 * LQ;                // 64 x LP
    __nv_bfloat16* Pl  = Ph + 64 * LP;
    float* row_m     = (float*)(Pl + 64 * LP);
    float* row_l     = row_m + 64;
    float* row_alpha = row_l + 64;
    float* red_max   = row_alpha + 64;   // [2][64]
    float* red_sum   = red_max + 128;    // [2][64]

    const int qt = (int)gridDim.x - 1 - (int)blockIdx.x;   // heavy tiles first
    const int h = blockIdx.y, b = blockIdx.z;
    const int kvh = h >> 2;
    const int tid = threadIdx.x, lane = tid & 31, wid = tid >> 5;
    const int wm = wid & 3, wn = wid >> 2;

    const size_t qoff  = (((size_t)b * NHH + h) * SS + (size_t)qt * 64) * HDD;
    const size_t kvoff = ((size_t)b * NKVV + kvh) * SS * HDD;

    // Load Q tile 64x128 hi/lo
#pragma unroll
    for (int j = 0; j < 4; j++) {
        const int i = tid + j * 256;
        const int r = i >> 4, c = (i & 15) << 3;
        *(uint4*)&Qh[r * LQ + c] = *(const uint4*)(g_Qbh + qoff + (size_t)r * HDD + c);
        *(uint4*)&Ql[r * LQ + c] = *(const uint4*)(g_Qbl + qoff + (size_t)r * HDD + c);
    }
    if (tid < 64) { row_m[tid] = -1e30f; row_l[tid] = 0.0f; }

    float O[8][4];
#pragma unroll
    for (int i = 0; i < 8; i++)
#pragma unroll
        for (int e = 0; e < 4; e++) O[i][e] = 0.0f;

    const int ntiles = qt + 1;

    const int ar   = wm * 16 + (lane & 15);
    const int ac   = (lane >> 4) << 3;
    const int brr  = (lane & 7) + ((lane & 16) ? 8 : 0);
    const int bc8  = (lane & 8) ? 8 : 0;
    const int par  = wm * 16 + (lane & 15);
    const int vr   = (lane & 7) + ((lane & 8) ? 8 : 0);
    const int vc8  = (lane & 16) ? 8 : 0;
    const int rloc = wm * 16 + (lane >> 2);

    for (int t = 0; t < ntiles; t++) {
        const int kv0 = t * 64;
        __syncthreads();                               // [1] prev PV done with KV

        // Load K tile 64x128 hi/lo (synchronous)
#pragma unroll
        for (int j = 0; j < 4; j++) {
            const int i = tid + j * 256;
            const int r = i >> 4, c = (i & 15) << 3;
            const size_t go = kvoff + (size_t)(kv0 + r) * HDD + c;
            *(uint4*)&KVh[r * LQ + c] = *(const uint4*)(g_Kbh + go);
            *(uint4*)&KVl[r * LQ + c] = *(const uint4*)(g_Kbl + go);
        }
        __syncthreads();                               // [2]

        // ---- QK^T: 16 rows x 32 kv per warp ----
        float sc[4][4];
#pragma unroll
        for (int nt = 0; nt < 4; nt++)
#pragma unroll
            for (int e = 0; e < 4; e++) sc[nt][e] = 0.0f;

#pragma unroll
        for (int ks = 0; ks < 8; ks++) {
            uint32_t aq[4], aql[4], bkA[4], bkB[4], bklA[4], bklB[4];
            ldm4(aq,   sptr(Qh  + ar * LQ + ks * 16 + ac));
            ldm4(aql,  sptr(Ql  + ar * LQ + ks * 16 + ac));
            ldm4(bkA,  sptr(KVh + (wn * 32 + brr)      * LQ + ks * 16 + bc8));
            ldm4(bkB,  sptr(KVh + (wn * 32 + 16 + brr) * LQ + ks * 16 + bc8));
            ldm4(bklA, sptr(KVl + (wn * 32 + brr)      * LQ + ks * 16 + bc8));
            ldm4(bklB, sptr(KVl + (wn * 32 + 16 + brr) * LQ + ks * 16 + bc8));
            mma_bf16(sc[0], aq,  bkA[0],  bkA[1]);
            mma_bf16(sc[1], aq,  bkA[2],  bkA[3]);
            mma_bf16(sc[2], aq,  bkB[0],  bkB[1]);
            mma_bf16(sc[3], aq,  bkB[2],  bkB[3]);
            mma_bf16(sc[0], aq,  bklA[0], bklA[1]);
            mma_bf16(sc[1], aq,  bklA[2], bklA[3]);
            mma_bf16(sc[2], aq,  bklB[0], bklB[1]);
            mma_bf16(sc[3], aq,  bklB[2], bklB[3]);
            mma_bf16(sc[0], aql, bkA[0],  bkA[1]);
            mma_bf16(sc[1], aql, bkA[2],  bkA[3]);
            mma_bf16(sc[2], aql, bkB[0],  bkB[1]);
            mma_bf16(sc[3], aql, bkB[2],  bkB[3]);
        }

        // ---- causal mask (Q pre-scaled) ----
        const int grow = qt * 64 + rloc;
        const int gcol = kv0 + wn * 32 + ((lane & 3) << 1);
#pragma unroll
        for (int nt = 0; nt < 4; nt++)
#pragma unroll
            for (int e = 0; e < 4; e++) {
                const int rr = grow + ((e & 2) ? 8 : 0);
                const int cc = gcol + nt * 8 + (e & 1);
                sc[nt][e] = (cc <= rr) ? sc[nt][e] : -1e30f;
            }

        // ---- row max ----
        float m0 = -1e30f, m1 = -1e30f;
#pragma unroll
        for (int nt = 0; nt < 4; nt++) {
            m0 = fmaxf(m0, fmaxf(sc[nt][0], sc[nt][1]));
            m1 = fmaxf(m1, fmaxf(sc[nt][2], sc[nt][3]));
        }
        m0 = fmaxf(m0, __shfl_xor_sync(0xffffffffu, m0, 1));
        m0 = fmaxf(m0, __shfl_xor_sync(0xffffffffu, m0, 2));
        m1 = fmaxf(m1, __shfl_xor_sync(0xffffffffu, m1, 1));
        m1 = fmaxf(m1, __shfl_xor_sync(0xffffffffu, m1, 2));
        if ((lane & 3) == 0) {
            red_max[wn * 64 + rloc]     = m0;
            red_max[wn * 64 + rloc + 8] = m1;
        }
        __syncthreads();                               // [3] all K reads complete

        // Issue V(t) async OVER the K buffer — hides under softmax/P phase
#pragma unroll
        for (int j = 0; j < 4; j++) {
            const int i = tid + j * 256;
            const int r = i >> 4, c = (i & 15) << 3;
            const size_t go = kvoff + (size_t)(kv0 + r) * HDD + c;
            cp16(sptr(KVh + r * LQ + c), g_Vbh + go);
            cp16(sptr(KVl + r * LQ + c), g_Vbl + go);
        }
        cp_commit();

        if (tid < 64) {
            const float mo = row_m[tid];
            const float mn = fmaxf(mo, fmaxf(red_max[tid], red_max[64 + tid]));
            row_alpha[tid] = __expf(mo - mn);
            row_m[tid] = mn;
        }
        __syncthreads();                               // [4]

        // ---- P = exp(s-m), split to smem, partial sums ----
        const float mr0 = row_m[rloc];
        const float mr1 = row_m[rloc + 8];
        float s0 = 0.0f, s1 = 0.0f;
#pragma unroll
        for (int nt = 0; nt < 4; nt++) {
            const float p0 = __expf(sc[nt][0] - mr0);
            const float p1 = __expf(sc[nt][1] - mr0);
            const float p2 = __expf(sc[nt][2] - mr1);
            const float p3 = __expf(sc[nt][3] - mr1);
            s0 += p0 + p1; s1 += p2 + p3;
            const int pc = wn * 32 + nt * 8 + ((lane & 3) << 1);
            __nv_bfloat16 h0, l0, h1, l1;
            split2(p0, h0, l0); split2(p1, h1, l1);
            *(__nv_bfloat162*)(Ph + rloc * LP + pc) = __halves2bfloat162(h0, h1);
            *(__nv_bfloat162*)(Pl + rloc * LP + pc) = __halves2bfloat162(l0, l1);
            split2(p2, h0, l0); split2(p3, h1, l1);
            *(__nv_bfloat162*)(Ph + (rloc + 8) * LP + pc) = __halves2bfloat162(h0, h1);
            *(__nv_bfloat162*)(Pl + (rloc + 8) * LP + pc) = __halves2bfloat162(l0, l1);
        }
        s0 += __shfl_xor_sync(0xffffffffu, s0, 1);
        s0 += __shfl_xor_sync(0xffffffffu, s0, 2);
        s1 += __shfl_xor_sync(0xffffffffu, s1, 1);
        s1 += __shfl_xor_sync(0xffffffffu, s1, 2);
        if ((lane & 3) == 0) {
            red_sum[wn * 64 + rloc]     = s0;
            red_sum[wn * 64 + rloc + 8] = s1;
        }
        __syncthreads();                               // [5] P visible
        if (tid < 64)
            row_l[tid] = row_l[tid] * row_alpha[tid] + red_sum[tid] + red_sum[64 + tid];

        // Wait for V(t) delivery
        cp_wait<0>();
        __syncthreads();                               // [6]

        // ---- rescale O, PV: 16 rows x 64 dims per warp, K-dim 64 ----
        const float a0 = row_alpha[rloc];
        const float a1 = row_alpha[rloc + 8];
#pragma unroll
        for (int nt = 0; nt < 8; nt++) {
            O[nt][0] *= a0; O[nt][1] *= a0; O[nt][2] *= a1; O[nt][3] *= a1;
        }
#pragma unroll
        for (int ks = 0; ks < 4; ks++) {
            uint32_t ap[4], apl[4];
            ldm4(ap,  sptr(Ph + par * LP + ks * 16 + ac));
            ldm4(apl, sptr(Pl + par * LP + ks * 16 + ac));
#pragma unroll
            for (int g = 0; g < 4; g++) {
                uint32_t bv[4], bvl[4];
                ldm4t(bv,  sptr(KVh + (ks * 16 + vr) * LQ + wn * 64 + g * 16 + vc8));
                ldm4t(bvl, sptr(KVl + (ks * 16 + vr) * LQ + wn * 64 + g * 16 + vc8));
                mma_bf16(O[g * 2 + 0], ap,  bv[0],  bv[1]);
                mma_bf16(O[g * 2 + 1], ap,  bv[2],  bv[3]);
                mma_bf16(O[g * 2 + 0], ap,  bvl[0], bvl[1]);
                mma_bf16(O[g * 2 + 1], ap,  bvl[2], bvl[3]);
                mma_bf16(O[g * 2 + 0], apl, bv[0],  bv[1]);
                mma_bf16(O[g * 2 + 1], apl, bv[2],  bv[3]);
            }
        }
    }

    __syncthreads();
    const float inv0 = 1.0f / row_l[rloc];
    const float inv1 = 1.0f / row_l[rloc + 8];
    const size_t ao = ((size_t)b * SS + (size_t)qt * 64) * HIDD + (size_t)h * HDD;
#pragma unroll
    for (int nt = 0; nt < 8; nt++) {
        const int cc = wn * 64 + nt * 8 + ((lane & 3) << 1);
        __nv_bfloat16 h0, l0, h1, l1;
        split2(O[nt][0] * inv0, h0, l0); split2(O[nt][1] * inv0, h1, l1);
        *(__nv_bfloat162*)(g_AOh + ao + (size_t)rloc * HIDD + cc) = __halves2bfloat162(h0, h1);
        *(__nv_bfloat162*)(g_AOl + ao + (size_t)rloc * HIDD + cc) = __halves2bfloat162(l0, l1);
        split2(O[nt][2] * inv1, h0, l0); split2(O[nt][3] * inv1, h1, l1);
        *(__nv_bfloat162*)(g_AOh + ao + (size_t)(rloc + 8) * HIDD + cc) = __halves2bfloat162(h0, h1);
        *(__nv_bfloat162*)(g_AOl + ao + (size_t)(rloc + 8) * HIDD + cc) = __halves2bfloat162(l0, l1);
    }
}

// ---------------------------------------------------------------------------
extern "C" void kernel_launch(void* const* d_in, const int* in_sizes, int n_in,
                              void* d_out, int out_size)
{
    (void)in_sizes; (void)n_in; (void)out_size;
    const float* hs = (const float*)d_in[0];
    const float* Wq = (const float*)d_in[1];
    const float* Wk = (const float*)d_in[2];
    const float* Wv = (const float*)d_in[3];
    const float* Wo = (const float*)d_in[4];
    float* out = (float*)d_out;

    const int M = BB * SS;  // 4096
    dim3 blk(256);

    const int attn_smem =
        (64 * LQ * 4 + 64 * LP * 2) * (int)sizeof(__nv_bfloat16) +
        (64 * 3 + 128 * 2) * (int)sizeof(float);
    cudaFuncSetAttribute(attn_mma, cudaFuncAttributeMaxDynamicSharedMemorySize, attn_smem);
    cudaFuncSetAttribute(gemm_qkv, cudaFuncAttributeMaxDynamicSharedMemorySize, GEMM_SMEM);
    cudaFuncSetAttribute(gemm_wo,  cudaFuncAttributeMaxDynamicSharedMemorySize, GEMM_SMEM);

    // RoPE table + input splits
    invf_kernel<<<1, 64>>>();
    split_kernel<<<(unsigned)(N_HS / 1024), blk>>>(hs, 0, N_HS);
    split_kernel<<<(unsigned)(N_WQ / 1024), blk>>>(Wq, 1, N_WQ);
    split_kernel<<<(unsigned)(N_WK / 1024), blk>>>(Wk, 2, N_WK);
    split_kernel<<<(unsigned)(N_WK / 1024), blk>>>(Wv, 3, N_WK);
    split_kernel<<<(unsigned)(N_WQ / 1024), blk>>>(Wo, 4, N_WQ);

    // Fused Q+K+V projections (one launch, 48x32 blocks)
    gemm_qkv<<<dim3(48, M / 128), blk, GEMM_SMEM>>>();

    // RoPE + split for Q/K
    rope_split_kernel<0><<<dim3(SS, NHH, BB), 64>>>();
    rope_split_kernel<1><<<dim3(SS, NKVV, BB), 64>>>();

    // Causal GQA flash attention -> g_AOh/g_AOl
    attn_mma<<<dim3(SS / 64, NHH, BB), blk, attn_smem>>>();

    // Output projection
    gemm_wo<<<dim3(HIDD / 128, M / 128), blk, GEMM_SMEM>>>(out);
}

// round 15
// speedup vs baseline: 1.0199x; 1.0012x over previous
#include <cuda_runtime.h>
#include <cuda_bf16.h>
#include <math.h>
#include <stdint.h>

// Problem constants
#define BB   2
#define SS   2048
#define HIDD 4096
#define NHH  32
#define NKVV 8
#define HDD  128
#define GG   4

#define N_HS ((size_t)BB * SS * HIDD)
#define N_WQ ((size_t)HIDD * HIDD)
#define N_WK ((size_t)NKVV * HDD * HIDD)
#define N_QB ((size_t)BB * NHH * SS * HDD)
#define N_KB ((size_t)BB * NKVV * SS * HDD)

// RoPE inverse-frequency table (double, precomputed once)
__device__ double g_invf[64];

// bf16 hi/lo split operands
__device__ __nv_bfloat16 g_hsh[N_HS],  g_hsl[N_HS];
__device__ __nv_bfloat16 g_Wqh[N_WQ],  g_Wql[N_WQ];
__device__ __nv_bfloat16 g_Wkh[N_WK],  g_Wkl[N_WK];
__device__ __nv_bfloat16 g_Wvh[N_WK],  g_Wvl[N_WK];
__device__ __nv_bfloat16 g_Woh[N_WQ],  g_Wol[N_WQ];
__device__ __nv_bfloat16 g_Qbh[N_QB],  g_Qbl[N_QB];   // post-RoPE, pre-scaled
__device__ __nv_bfloat16 g_Kbh[N_KB],  g_Kbl[N_KB];   // post-RoPE
__device__ __nv_bfloat16 g_Vbh[N_KB],  g_Vbl[N_KB];
__device__ __nv_bfloat16 g_AOh[N_HS],  g_AOl[N_HS];   // attention output

// ---------------------------------------------------------------------------
// helpers
// ---------------------------------------------------------------------------
__device__ __forceinline__ uint32_t sptr(const void* p) {
    return (uint32_t)__cvta_generic_to_shared(p);
}
__device__ __forceinline__ void cp16(uint32_t d, const void* s) {
    asm volatile("cp.async.cg.shared.global [%0], [%1], 16;\n" :: "r"(d), "l"(s));
}
__device__ __forceinline__ void cp_commit() { asm volatile("cp.async.commit_group;\n"); }
template <int N> __device__ __forceinline__ void cp_wait() {
    asm volatile("cp.async.wait_group %0;\n" :: "n"(N));
}
__device__ __forceinline__ void ldm4(uint32_t* r, uint32_t a) {
    asm volatile("ldmatrix.sync.aligned.m8n8.x4.shared.b16 {%0,%1,%2,%3}, [%4];\n"
        : "=r"(r[0]), "=r"(r[1]), "=r"(r[2]), "=r"(r[3]) : "r"(a));
}
__device__ __forceinline__ void ldm4t(uint32_t* r, uint32_t a) {
    asm volatile("ldmatrix.sync.aligned.m8n8.x4.trans.shared.b16 {%0,%1,%2,%3}, [%4];\n"
        : "=r"(r[0]), "=r"(r[1]), "=r"(r[2]), "=r"(r[3]) : "r"(a));
}
__device__ __forceinline__ void mma_bf16(float* c, const uint32_t* a, uint32_t b0, uint32_t b1) {
    asm volatile(
        "mma.sync.aligned.m16n8k16.row.col.f32.bf16.bf16.f32 "
        "{%0,%1,%2,%3}, {%4,%5,%6,%7}, {%8,%9}, {%0,%1,%2,%3};\n"
        : "+f"(c[0]), "+f"(c[1]), "+f"(c[2]), "+f"(c[3])
        : "r"(a[0]), "r"(a[1]), "r"(a[2]), "r"(a[3]), "r"(b0), "r"(b1));
}
__device__ __forceinline__ void split2(float x, __nv_bfloat16& h, __nv_bfloat16& l) {
    h = __float2bfloat16(x);
    l = __float2bfloat16(x - __bfloat162float(h));
}

// ---------------------------------------------------------------------------
// Precompute inv-freq table (same expression -> bit-identical phases)
// ---------------------------------------------------------------------------
__global__ void invf_kernel()
{
    const int d = threadIdx.x;  // 0..63
    g_invf[d] = pow(10000.0, -(double)d / 64.0);
}

// ---------------------------------------------------------------------------
// Elementwise fp32 -> bf16 hi/lo split (inputs only).
// ---------------------------------------------------------------------------
__global__ void __launch_bounds__(256) split_kernel(const float* __restrict__ src,
                                                    int dsel, size_t n)
{
    __nv_bfloat16 *dh, *dl;
    switch (dsel) {
        case 1: dh = g_Wqh; dl = g_Wql; break;
        case 2: dh = g_Wkh; dl = g_Wkl; break;
        case 3: dh = g_Wvh; dl = g_Wvl; break;
        case 4: dh = g_Woh; dl = g_Wol; break;
        default: dh = g_hsh; dl = g_hsl; break;
    }
    const size_t i = ((size_t)blockIdx.x * 256 + threadIdx.x) * 4;
    if (i >= n) return;
    float4 v = *(const float4*)(src + i);
    __nv_bfloat16 h0, l0, h1, l1, h2, l2, h3, l3;
    split2(v.x, h0, l0); split2(v.y, h1, l1);
    split2(v.z, h2, l2); split2(v.w, h3, l3);
    ushort4 uh, ul;
    uh.x = __bfloat16_as_ushort(h0); uh.y = __bfloat16_as_ushort(h1);
    uh.z = __bfloat16_as_ushort(h2); uh.w = __bfloat16_as_ushort(h3);
    ul.x = __bfloat16_as_ushort(l0); ul.y = __bfloat16_as_ushort(l1);
    ul.z = __bfloat16_as_ushort(l2); ul.w = __bfloat16_as_ushort(l3);
    *(ushort4*)(dh + i) = uh;
    *(ushort4*)(dl + i) = ul;
}

// ---------------------------------------------------------------------------
// Shared GEMM structure (bf16 3-term, 128x128 tile, 2-stage).
// ---------------------------------------------------------------------------
#define LDP 40
#define XS_ELEM (128 * LDP)                       // 5120
#define STAGE_ELEM (4 * XS_ELEM)                  // 20480
#define GEMM_SMEM (2 * STAGE_ELEM * 2)            // 81920 bytes

// ---------------------------------------------------------------------------
// Fused QKV projection with in-epilogue RoPE.
//   bx in [0,32)  -> Wq: RoPE (scaled) -> g_Qbh/g_Qbl
//   bx in [32,40) -> Wk: RoPE          -> g_Kbh/g_Kbl
//   bx in [40,48) -> Wv: plain split   -> g_Vbh/g_Vbl
// RoPE epilogue: stage fp32 tile in smem (128 x 132 = 67.6 KB, reusing the
// pipeline buffers), then rotate (d, d+64) pairs and write split bf16.
// Identical fp32 values / op order as the old rope_split kernel.
// ---------------------------------------------------------------------------
__global__ void __launch_bounds__(256, 2) gemm_qkv()
{
    extern __shared__ __align__(16) __nv_bfloat16 sm[];

    const int bx = blockIdx.x;
    const __nv_bfloat16 *Bh_g, *Bl_g;
    int bn, path;   // path 0=Q, 1=K, 2=V
    if (bx < 32)      { Bh_g = g_Wqh; Bl_g = g_Wql; bn = bx * 128;        path = 0; }
    else if (bx < 40) { Bh_g = g_Wkh; Bl_g = g_Wkl; bn = (bx - 32) * 128; path = 1; }
    else              { Bh_g = g_Wvh; Bl_g = g_Wvl; bn = (bx - 40) * 128; path = 2; }

    const __nv_bfloat16* Ah_g = g_hsh;
    const __nv_bfloat16* Al_g = g_hsl;

    const int bm = blockIdx.y * 128;
    const int K = HIDD;
    const int tid = threadIdx.x;
    const int lane = tid & 31;
    const int wid = tid >> 5;
    const int wm = wid & 1;
    const int wn = wid >> 1;

    float acc[4][4][4];
#pragma unroll
    for (int i = 0; i < 4; i++)
#pragma unroll
        for (int j = 0; j < 4; j++)
#pragma unroll
            for (int e = 0; e < 4; e++) acc[i][j][e] = 0.0f;

    const int r0_ = tid >> 2, c0_ = (tid & 3) << 3;
    const int r1_ = (tid + 256) >> 2, c1_ = ((tid + 256) & 3) << 3;

    const int nk = K / 32;

    auto load_stage = [&](int stage, int k0) {
        __nv_bfloat16* Xh = sm + (size_t)stage * STAGE_ELEM;
        __nv_bfloat16* Xl = Xh + XS_ELEM;
        __nv_bfloat16* Wh = Xl + XS_ELEM;
        __nv_bfloat16* Wl = Wh + XS_ELEM;
        cp16(sptr(Xh + r0_ * LDP + c0_), Ah_g + (size_t)(bm + r0_) * K + k0 + c0_);
        cp16(sptr(Xh + r1_ * LDP + c1_), Ah_g + (size_t)(bm + r1_) * K + k0 + c1_);
        cp16(sptr(Xl + r0_ * LDP + c0_), Al_g + (size_t)(bm + r0_) * K + k0 + c0_);
        cp16(sptr(Xl + r1_ * LDP + c1_), Al_g + (size_t)(bm + r1_) * K + k0 + c1_);
        cp16(sptr(Wh + r0_ * LDP + c0_), Bh_g + (size_t)(bn + r0_) * K + k0 + c0_);
        cp16(sptr(Wh + r1_ * LDP + c1_), Bh_g + (size_t)(bn + r1_) * K + k0 + c1_);
        cp16(sptr(Wl + r0_ * LDP + c0_), Bl_g + (size_t)(bn + r0_) * K + k0 + c0_);
        cp16(sptr(Wl + r1_ * LDP + c1_), Bl_g + (size_t)(bn + r1_) * K + k0 + c1_);
        cp_commit();
    };

    load_stage(0, 0);

    const int arow = wm * 64 + (lane & 15);
    const int acol = (lane >> 4) << 3;
    const int brow = wn * 32 + (lane & 7) + ((lane & 16) ? 8 : 0);
    const int bc8  = (lane & 8) ? 8 : 0;

    for (int kt = 0; kt < nk; kt++) {
        const int cur = kt & 1;
        if (kt + 1 < nk) load_stage(cur ^ 1, (kt + 1) * 32);
        if (kt + 1 < nk) cp_wait<1>(); else cp_wait<0>();
        __syncthreads();

        __nv_bfloat16* Xh = sm + (size_t)cur * STAGE_ELEM;
        __nv_bfloat16* Xl = Xh + XS_ELEM;
        __nv_bfloat16* Wh = Xl + XS_ELEM;
        __nv_bfloat16* Wl = Wh + XS_ELEM;

#pragma unroll
        for (int ks = 0; ks < 2; ks++) {
            const int kc = ks * 16;
            uint32_t ah[4][4], al[4][4];
#pragma unroll
            for (int mt = 0; mt < 4; mt++) {
                ldm4(ah[mt], sptr(Xh + (arow + mt * 16) * LDP + kc + acol));
                ldm4(al[mt], sptr(Xl + (arow + mt * 16) * LDP + kc + acol));
            }
            uint32_t bh[4][2], bl[4][2];
            {
                uint32_t t[4];
                ldm4(t, sptr(Wh + brow * LDP + kc + bc8));
                bh[0][0] = t[0]; bh[0][1] = t[1]; bh[1][0] = t[2]; bh[1][1] = t[3];
                ldm4(t, sptr(Wh + (brow + 16) * LDP + kc + bc8));
                bh[2][0] = t[0]; bh[2][1] = t[1]; bh[3][0] = t[2]; bh[3][1] = t[3];
                ldm4(t, sptr(Wl + brow * LDP + kc + bc8));
                bl[0][0] = t[0]; bl[0][1] = t[1]; bl[1][0] = t[2]; bl[1][1] = t[3];
                ldm4(t, sptr(Wl + (brow + 16) * LDP + kc + bc8));
                bl[2][0] = t[0]; bl[2][1] = t[1]; bl[3][0] = t[2]; bl[3][1] = t[3];
            }
#pragma unroll
            for (int mt = 0; mt < 4; mt++)
#pragma unroll
                for (int nt = 0; nt < 4; nt++) {
                    mma_bf16(acc[mt][nt], ah[mt], bh[nt][0], bh[nt][1]);
                    mma_bf16(acc[mt][nt], ah[mt], bl[nt][0], bl[nt][1]);
                    mma_bf16(acc[mt][nt], al[mt], bh[nt][0], bh[nt][1]);
                }
        }
        __syncthreads();
    }

    if (path == 2) {
        // V: split directly from registers to bf16 hi/lo in [B,NKV,S,HD]
#pragma unroll
        for (int mt = 0; mt < 4; mt++) {
#pragma unroll
            for (int nt = 0; nt < 4; nt++) {
                const int r0 = bm + wm * 64 + mt * 16 + (lane >> 2);
                const int c0 = bn + wn * 32 + nt * 8 + ((lane & 3) << 1);
                const int h0 = c0 / HDD, d0 = c0 % HDD;
                const int b0i = r0 / SS, s0 = r0 % SS;
                const int r1 = r0 + 8;
                const int b1i = r1 / SS, s1 = r1 % SS;
                const size_t i0 = (((size_t)b0i * NKVV + h0) * SS + s0) * HDD + d0;
                __nv_bfloat16 h_, l_, h2_, l2_;
                split2(acc[mt][nt][0], h_, l_);
                split2(acc[mt][nt][1], h2_, l2_);
                *(__nv_bfloat162*)(g_Vbh + i0) = __halves2bfloat162(h_, h2_);
                *(__nv_bfloat162*)(g_Vbl + i0) = __halves2bfloat162(l_, l2_);
                const size_t i1 = (((size_t)b1i * NKVV + h0) * SS + s1) * HDD + d0;
                split2(acc[mt][nt][2], h_, l_);
                split2(acc[mt][nt][3], h2_, l2_);
                *(__nv_bfloat162*)(g_Vbh + i1) = __halves2bfloat162(h_, h2_);
                *(__nv_bfloat162*)(g_Vbl + i1) = __halves2bfloat162(l_, l2_);
            }
        }
    } else {
        // Q/K: stage fp32 tile in smem, then fused RoPE + split.
        float* ftile = (float*)sm;   // 128 x 132 floats = 67.6 KB
#pragma unroll
        for (int mt = 0; mt < 4; mt++) {
#pragma unroll
            for (int nt = 0; nt < 4; nt++) {
                const int rl = wm * 64 + mt * 16 + (lane >> 2);
                const int cl = wn * 32 + nt * 8 + ((lane & 3) << 1);
                *(float2*)&ftile[rl * 132 + cl]       = make_float2(acc[mt][nt][0], acc[mt][nt][1]);
                *(float2*)&ftile[(rl + 8) * 132 + cl] = make_float2(acc[mt][nt][2], acc[mt][nt][3]);
            }
        }
        __syncthreads();

        const int hh = bn >> 7;                       // head index within tensor
        const int H = (path == 0) ? NHH : NKVV;
        __nv_bfloat16* Dh = (path == 0) ? g_Qbh : g_Kbh;
        __nv_bfloat16* Dl = (path == 0) ? g_Qbl : g_Kbl;

#pragma unroll 4
        for (int k = 0; k < 32; k++) {
            const int idx = tid + k * 256;            // 0..8191
            const int r = idx >> 6, d = idx & 63;
            const int rg = bm + r;
            const int b = rg / SS, s = rg % SS;
            const float x1 = ftile[r * 132 + d];
            const float x2 = ftile[r * 132 + d + 64];
            const float f = (float)((double)s * g_invf[d]);
            float sn, cs;
            sincosf(f, &sn, &cs);
            float y1 = x1 * cs - x2 * sn;
            float y2 = x2 * cs + x1 * sn;
            if (path == 0) { y1 *= 0.08838834764831845f; y2 *= 0.08838834764831845f; }
            const size_t base = (((size_t)b * H + hh) * SS + s) * HDD;
            __nv_bfloat16 h_, l_;
            split2(y1, h_, l_); Dh[base + d] = h_;      Dl[base + d] = l_;
            split2(y2, h_, l_); Dh[base + d + 64] = h_; Dl[base + d + 64] = l_;
        }
    }
}

// ---------------------------------------------------------------------------
// Output projection GEMM: out = AO @ Wo^T (fp32 row-major out).
// ---------------------------------------------------------------------------
__global__ void __launch_bounds__(256, 2) gemm_wo(float* __restrict__ Y)
{
    extern __shared__ __align__(16) __nv_bfloat16 sm[];

    const __nv_bfloat16* Ah_g = g_AOh;
    const __nv_bfloat16* Al_g = g_AOl;
    const __nv_bfloat16* Bh_g = g_Woh;
    const __nv_bfloat16* Bl_g = g_Wol;

    const int bm = blockIdx.y * 128;
    const int bn = blockIdx.x * 128;
    const int K = HIDD, N = HIDD;
    const int tid = threadIdx.x;
    const int lane = tid & 31;
    const int wid = tid >> 5;
    const int wm = wid & 1;
    const int wn = wid >> 1;

    float acc[4][4][4];
#pragma unroll
    for (int i = 0; i < 4; i++)
#pragma unroll
        for (int j = 0; j < 4; j++)
#pragma unroll
            for (int e = 0; e < 4; e++) acc[i][j][e] = 0.0f;

    const int r0_ = tid >> 2, c0_ = (tid & 3) << 3;
    const int r1_ = (tid + 256) >> 2, c1_ = ((tid + 256) & 3) << 3;

    const int nk = K / 32;

    auto load_stage = [&](int stage, int k0) {
        __nv_bfloat16* Xh = sm + (size_t)stage * STAGE_ELEM;
        __nv_bfloat16* Xl = Xh + XS_ELEM;
        __nv_bfloat16* Wh = Xl + XS_ELEM;
        __nv_bfloat16* Wl = Wh + XS_ELEM;
        cp16(sptr(Xh + r0_ * LDP + c0_), Ah_g + (size_t)(bm + r0_) * K + k0 + c0_);
        cp16(sptr(Xh + r1_ * LDP + c1_), Ah_g + (size_t)(bm + r1_) * K + k0 + c1_);
        cp16(sptr(Xl + r0_ * LDP + c0_), Al_g + (size_t)(bm + r0_) * K + k0 + c0_);
        cp16(sptr(Xl + r1_ * LDP + c1_), Al_g + (size_t)(bm + r1_) * K + k0 + c1_);
        cp16(sptr(Wh + r0_ * LDP + c0_), Bh_g + (size_t)(bn + r0_) * K + k0 + c0_);
        cp16(sptr(Wh + r1_ * LDP + c1_), Bh_g + (size_t)(bn + r1_) * K + k0 + c1_);
        cp16(sptr(Wl + r0_ * LDP + c0_), Bl_g + (size_t)(bn + r0_) * K + k0 + c0_);
        cp16(sptr(Wl + r1_ * LDP + c1_), Bl_g + (size_t)(bn + r1_) * K + k0 + c1_);
        cp_commit();
    };

    load_stage(0, 0);

    const int arow = wm * 64 + (lane & 15);
    const int acol = (lane >> 4) << 3;
    const int brow = wn * 32 + (lane & 7) + ((lane & 16) ? 8 : 0);
    const int bc8  = (lane & 8) ? 8 : 0;

    for (int kt = 0; kt < nk; kt++) {
        const int cur = kt & 1;
        if (kt + 1 < nk) load_stage(cur ^ 1, (kt + 1) * 32);
        if (kt + 1 < nk) cp_wait<1>(); else cp_wait<0>();
        __syncthreads();

        __nv_bfloat16* Xh = sm + (size_t)cur * STAGE_ELEM;
        __nv_bfloat16* Xl = Xh + XS_ELEM;
        __nv_bfloat16* Wh = Xl + XS_ELEM;
        __nv_bfloat16* Wl = Wh + XS_ELEM;

#pragma unroll
        for (int ks = 0; ks < 2; ks++) {
            const int kc = ks * 16;
            uint32_t ah[4][4], al[4][4];
#pragma unroll
            for (int mt = 0; mt < 4; mt++) {
                ldm4(ah[mt], sptr(Xh + (arow + mt * 16) * LDP + kc + acol));
                ldm4(al[mt], sptr(Xl + (arow + mt * 16) * LDP + kc + acol));
            }
            uint32_t bh[4][2], bl[4][2];
            {
                uint32_t t[4];
                ldm4(t, sptr(Wh + brow * LDP + kc + bc8));
                bh[0][0] = t[0]; bh[0][1] = t[1]; bh[1][0] = t[2]; bh[1][1] = t[3];
                ldm4(t, sptr(Wh + (brow + 16) * LDP + kc + bc8));
                bh[2][0] = t[0]; bh[2][1] = t[1]; bh[3][0] = t[2]; bh[3][1] = t[3];
                ldm4(t, sptr(Wl + brow * LDP + kc + bc8));
                bl[0][0] = t[0]; bl[0][1] = t[1]; bl[1][0] = t[2]; bl[1][1] = t[3];
                ldm4(t, sptr(Wl + (brow + 16) * LDP + kc + bc8));
                bl[2][0] = t[0]; bl[2][1] = t[1]; bl[3][0] = t[2]; bl[3][1] = t[3];
            }
#pragma unroll
            for (int mt = 0; mt < 4; mt++)
#pragma unroll
                for (int nt = 0; nt < 4; nt++) {
                    mma_bf16(acc[mt][nt], ah[mt], bh[nt][0], bh[nt][1]);
                    mma_bf16(acc[mt][nt], ah[mt], bl[nt][0], bl[nt][1]);
                    mma_bf16(acc[mt][nt], al[mt], bh[nt][0], bh[nt][1]);
                }
        }
        __syncthreads();
    }

#pragma unroll
    for (int mt = 0; mt < 4; mt++) {
#pragma unroll
        for (int nt = 0; nt < 4; nt++) {
            const int r0 = bm + wm * 64 + mt * 16 + (lane >> 2);
            const int c0 = bn + wn * 32 + nt * 8 + ((lane & 3) << 1);
            *(float2*)(Y + (size_t)r0 * N + c0)       = make_float2(acc[mt][nt][0], acc[mt][nt][1]);
            *(float2*)(Y + (size_t)(r0 + 8) * N + c0) = make_float2(acc[mt][nt][2], acc[mt][nt][3]);
        }
    }
}

// ---------------------------------------------------------------------------
// Flash attention — unchanged from R14 (shared KV buffer, async V prefetch,
// reverse-qt load balance).
// ---------------------------------------------------------------------------
#define LQ 136
#define LP 72

__global__ void __launch_bounds__(256) attn_mma()
{
    extern __shared__ __align__(16) char smraw[];
    __nv_bfloat16* Qh  = (__nv_bfloat16*)smraw;        // 64 x LQ
    __nv_bfloat16* Ql  = Qh + 64 * LQ;
    __nv_bfloat16* KVh = Ql + 64 * LQ;                 // 64 x LQ (K then V)
    __nv_bfloat16* KVl = KVh + 64 * LQ;
    __nv_bfloat16* Ph  = KVl + 64 * LQ;                // 64 x LP
    __nv_bfloat16* Pl  = Ph + 64 * LP;
    float* row_m     = (float*)(Pl + 64 * LP);
    float* row_l     = row_m + 64;
    float* row_alpha = row_l + 64;
    float* red_max   = row_alpha + 64;   // [2][64]
    float* red_sum   = red_max + 128;    // [2][64]

    const int qt = (int)gridDim.x - 1 - (int)blockIdx.x;   // heavy tiles first
    const int h = blockIdx.y, b = blockIdx.z;
    const int kvh = h >> 2;
    const int tid = threadIdx.x, lane = tid & 31, wid = tid >> 5;
    const int wm = wid & 3, wn = wid >> 2;

    const size_t qoff  = (((size_t)b * NHH + h) * SS + (size_t)qt * 64) * HDD;
    const size_t kvoff = ((size_t)b * NKVV + kvh) * SS * HDD;

#pragma unroll
    for (int j = 0; j < 4; j++) {
        const int i = tid + j * 256;
        const int r = i >> 4, c = (i & 15) << 3;
        *(uint4*)&Qh[r * LQ + c] = *(const uint4*)(g_Qbh + qoff + (size_t)r * HDD + c);
        *(uint4*)&Ql[r * LQ + c] = *(const uint4*)(g_Qbl + qoff + (size_t)r * HDD + c);
    }
    if (tid < 64) { row_m[tid] = -1e30f; row_l[tid] = 0.0f; }

    float O[8][4];
#pragma unroll
    for (int i = 0; i < 8; i++)
#pragma unroll
        for (int e = 0; e < 4; e++) O[i][e] = 0.0f;

    const int ntiles = qt + 1;

    const int ar   = wm * 16 + (lane & 15);
    const int ac   = (lane >> 4) << 3;
    const int brr  = (lane & 7) + ((lane & 16) ? 8 : 0);
    const int bc8  = (lane & 8) ? 8 : 0;
    const int par  = wm * 16 + (lane & 15);
    const int vr   = (lane & 7) + ((lane & 8) ? 8 : 0);
    const int vc8  = (lane & 16) ? 8 : 0;
    const int rloc = wm * 16 + (lane >> 2);

    for (int t = 0; t < ntiles; t++) {
        const int kv0 = t * 64;
        __syncthreads();                               // [1] prev PV done with KV

#pragma unroll
        for (int j = 0; j < 4; j++) {
            const int i = tid + j * 256;
            const int r = i >> 4, c = (i & 15) << 3;
            const size_t go = kvoff + (size_t)(kv0 + r) * HDD + c;
            *(uint4*)&KVh[r * LQ + c] = *(const uint4*)(g_Kbh + go);
            *(uint4*)&KVl[r * LQ + c] = *(const uint4*)(g_Kbl + go);
        }
        __syncthreads();                               // [2]

        float sc[4][4];
#pragma unroll
        for (int nt = 0; nt < 4; nt++)
#pragma unroll
            for (int e = 0; e < 4; e++) sc[nt][e] = 0.0f;

#pragma unroll
        for (int ks = 0; ks < 8; ks++) {
            uint32_t aq[4], aql[4], bkA[4], bkB[4], bklA[4], bklB[4];
            ldm4(aq,   sptr(Qh  + ar * LQ + ks * 16 + ac));
            ldm4(aql,  sptr(Ql  + ar * LQ + ks * 16 + ac));
            ldm4(bkA,  sptr(KVh + (wn * 32 + brr)      * LQ + ks * 16 + bc8));
            ldm4(bkB,  sptr(KVh + (wn * 32 + 16 + brr) * LQ + ks * 16 + bc8));
            ldm4(bklA, sptr(KVl + (wn * 32 + brr)      * LQ + ks * 16 + bc8));
            ldm4(bklB, sptr(KVl + (wn * 32 + 16 + brr) * LQ + ks * 16 + bc8));
            mma_bf16(sc[0], aq,  bkA[0],  bkA[1]);
            mma_bf16(sc[1], aq,  bkA[2],  bkA[3]);
            mma_bf16(sc[2], aq,  bkB[0],  bkB[1]);
            mma_bf16(sc[3], aq,  bkB[2],  bkB[3]);
            mma_bf16(sc[0], aq,  bklA[0], bklA[1]);
            mma_bf16(sc[1], aq,  bklA[2], bklA[3]);
            mma_bf16(sc[2], aq,  bklB[0], bklB[1]);
            mma_bf16(sc[3], aq,  bklB[2], bklB[3]);
            mma_bf16(sc[0], aql, bkA[0],  bkA[1]);
            mma_bf16(sc[1], aql, bkA[2],  bkA[3]);
            mma_bf16(sc[2], aql, bkB[0],  bkB[1]);
            mma_bf16(sc[3], aql, bkB[2],  bkB[3]);
        }

        const int grow = qt * 64 + rloc;
        const int gcol = kv0 + wn * 32 + ((lane & 3) << 1);
#pragma unroll
        for (int nt = 0; nt < 4; nt++)
#pragma unroll
            for (int e = 0; e < 4; e++) {
                const int rr = grow + ((e & 2) ? 8 : 0);
                const int cc = gcol + nt * 8 + (e & 1);
                sc[nt][e] = (cc <= rr) ? sc[nt][e] : -1e30f;
            }

        float m0 = -1e30f, m1 = -1e30f;
#pragma unroll
        for (int nt = 0; nt < 4; nt++) {
            m0 = fmaxf(m0, fmaxf(sc[nt][0], sc[nt][1]));
            m1 = fmaxf(m1, fmaxf(sc[nt][2], sc[nt][3]));
        }
        m0 = fmaxf(m0, __shfl_xor_sync(0xffffffffu, m0, 1));
        m0 = fmaxf(m0, __shfl_xor_sync(0xffffffffu, m0, 2));
        m1 = fmaxf(m1, __shfl_xor_sync(0xffffffffu, m1, 1));
        m1 = fmaxf(m1, __shfl_xor_sync(0xffffffffu, m1, 2));
        if ((lane & 3) == 0) {
            red_max[wn * 64 + rloc]     = m0;
            red_max[wn * 64 + rloc + 8] = m1;
        }
        __syncthreads();                               // [3] all K reads complete

        // Issue V(t) async OVER the K buffer
#pragma unroll
        for (int j = 0; j < 4; j++) {
            const int i = tid + j * 256;
            const int r = i >> 4, c = (i & 15) << 3;
            const size_t go = kvoff + (size_t)(kv0 + r) * HDD + c;
            cp16(sptr(KVh + r * LQ + c), g_Vbh + go);
            cp16(sptr(KVl + r * LQ + c), g_Vbl + go);
        }
        cp_commit();

        if (tid < 64) {
            const float mo = row_m[tid];
            const float mn = fmaxf(mo, fmaxf(red_max[tid], red_max[64 + tid]));
            row_alpha[tid] = __expf(mo - mn);
            row_m[tid] = mn;
        }
        __syncthreads();                               // [4]

        const float mr0 = row_m[rloc];
        const float mr1 = row_m[rloc + 8];
        float s0 = 0.0f, s1 = 0.0f;
#pragma unroll
        for (int nt = 0; nt < 4; nt++) {
            const float p0 = __expf(sc[nt][0] - mr0);
            const float p1 = __expf(sc[nt][1] - mr0);
            const float p2 = __expf(sc[nt][2] - mr1);
            const float p3 = __expf(sc[nt][3] - mr1);
            s0 += p0 + p1; s1 += p2 + p3;
            const int pc = wn * 32 + nt * 8 + ((lane & 3) << 1);
            __nv_bfloat16 h0, l0, h1, l1;
            split2(p0, h0, l0); split2(p1, h1, l1);
            *(__nv_bfloat162*)(Ph + rloc * LP + pc) = __halves2bfloat162(h0, h1);
            *(__nv_bfloat162*)(Pl + rloc * LP + pc) = __halves2bfloat162(l0, l1);
            split2(p2, h0, l0); split2(p3, h1, l1);
            *(__nv_bfloat162*)(Ph + (rloc + 8) * LP + pc) = __halves2bfloat162(h0, h1);
            *(__nv_bfloat162*)(Pl + (rloc + 8) * LP + pc) = __halves2bfloat162(l0, l1);
        }
        s0 += __shfl_xor_sync(0xffffffffu, s0, 1);
        s0 += __shfl_xor_sync(0xffffffffu, s0, 2);
        s1 += __shfl_xor_sync(0xffffffffu, s1, 1);
        s1 += __shfl_xor_sync(0xffffffffu, s1, 2);
        if ((lane & 3) == 0) {
            red_sum[wn * 64 + rloc]     = s0;
            red_sum[wn * 64 + rloc + 8] = s1;
        }
        __syncthreads();                               // [5] P visible
        if (tid < 64)
            row_l[tid] = row_l[tid] * row_alpha[tid] + red_sum[tid] + red_sum[64 + tid];

        cp_wait<0>();
        __syncthreads();                               // [6] V ready

        const float a0 = row_alpha[rloc];
        const float a1 = row_alpha[rloc + 8];
#pragma unroll
        for (int nt = 0; nt < 8; nt++) {
            O[nt][0] *= a0; O[nt][1] *= a0; O[nt][2] *= a1; O[nt][3] *= a1;
        }
#pragma unroll
        for (int ks = 0; ks < 4; ks++) {
            uint32_t ap[4], apl[4];
            ldm4(ap,  sptr(Ph + par * LP + ks * 16 + ac));
            ldm4(apl, sptr(Pl + par * LP + ks * 16 + ac));
#pragma unroll
            for (int g = 0; g < 4; g++) {
                uint32_t bv[4], bvl[4];
                ldm4t(bv,  sptr(KVh + (ks * 16 + vr) * LQ + wn * 64 + g * 16 + vc8));
                ldm4t(bvl, sptr(KVl + (ks * 16 + vr) * LQ + wn * 64 + g * 16 + vc8));
                mma_bf16(O[g * 2 + 0], ap,  bv[0],  bv[1]);
                mma_bf16(O[g * 2 + 1], ap,  bv[2],  bv[3]);
                mma_bf16(O[g * 2 + 0], ap,  bvl[0], bvl[1]);
                mma_bf16(O[g * 2 + 1], ap,  bvl[2], bvl[3]);
                mma_bf16(O[g * 2 + 0], apl, bv[0],  bv[1]);
                mma_bf16(O[g * 2 + 1], apl, bv[2],  bv[3]);
            }
        }
    }

    __syncthreads();
    const float inv0 = 1.0f / row_l[rloc];
    const float inv1 = 1.0f / row_l[rloc + 8];
    const size_t ao = ((size_t)b * SS + (size_t)qt * 64) * HIDD + (size_t)h * HDD;
#pragma unroll
    for (int nt = 0; nt < 8; nt++) {
        const int cc = wn * 64 + nt * 8 + ((lane & 3) << 1);
        __nv_bfloat16 h0, l0, h1, l1;
        split2(O[nt][0] * inv0, h0, l0); split2(O[nt][1] * inv0, h1, l1);
        *(__nv_bfloat162*)(g_AOh + ao + (size_t)rloc * HIDD + cc) = __halves2bfloat162(h0, h1);
        *(__nv_bfloat162*)(g_AOl + ao + (size_t)rloc * HIDD + cc) = __halves2bfloat162(l0, l1);
        split2(O[nt][2] * inv1, h0, l0); split2(O[nt][3] * inv1, h1, l1);
        *(__nv_bfloat162*)(g_AOh + ao + (size_t)(rloc + 8) * HIDD + cc) = __halves2bfloat162(h0, h1);
        *(__nv_bfloat162*)(g_AOl + ao + (size_t)(rloc + 8) * HIDD + cc) = __halves2bfloat162(l0, l1);
    }
}

// ---------------------------------------------------------------------------
extern "C" void kernel_launch(void* const* d_in, const int* in_sizes, int n_in,
                              void* d_out, int out_size)
{
    (void)in_sizes; (void)n_in; (void)out_size;
    const float* hs = (const float*)d_in[0];
    const float* Wq = (const float*)d_in[1];
    const float* Wk = (const float*)d_in[2];
    const float* Wv = (const float*)d_in[3];
    const float* Wo = (const float*)d_in[4];
    float* out = (float*)d_out;

    const int M = BB * SS;  // 4096
    dim3 blk(256);

    const int attn_smem =
        (64 * LQ * 4 + 64 * LP * 2) * (int)sizeof(__nv_bfloat16) +
        (64 * 3 + 128 * 2) * (int)sizeof(float);
    cudaFuncSetAttribute(attn_mma, cudaFuncAttributeMaxDynamicSharedMemorySize, attn_smem);
    cudaFuncSetAttribute(gemm_qkv, cudaFuncAttributeMaxDynamicSharedMemorySize, GEMM_SMEM);
    cudaFuncSetAttribute(gemm_wo,  cudaFuncAttributeMaxDynamicSharedMemorySize, GEMM_SMEM);

    // RoPE table + input splits
    invf_kernel<<<1, 64>>>();
    split_kernel<<<(unsigned)(N_HS / 1024), blk>>>(hs, 0, N_HS);
    split_kernel<<<(unsigned)(N_WQ / 1024), blk>>>(Wq, 1, N_WQ);
    split_kernel<<<(unsigned)(N_WK / 1024), blk>>>(Wk, 2, N_WK);
    split_kernel<<<(unsigned)(N_WK / 1024), blk>>>(Wv, 3, N_WK);
    split_kernel<<<(unsigned)(N_WQ / 1024), blk>>>(Wo, 4, N_WQ);

    // Fused Q+K+V projections with in-epilogue RoPE (one launch)
    gemm_qkv<<<dim3(48, M / 128), blk, GEMM_SMEM>>>();

    // Causal GQA flash attention -> g_AOh/g_AOl
    attn_mma<<<dim3(SS / 64, NHH, BB), blk, attn_smem>>>();

    // Output projection
    gemm_wo<<<dim3(HIDD / 128, M / 128), blk, GEMM_SMEM>>>(out);
}